// round 7
// baseline (speedup 1.0000x reference)
#include <cuda_runtime.h>

#define B_    32
#define C_    256
#define L_    336
#define O_    96
#define KC_   4
#define NL_   2
#define DFF_  1024
#define PROWS 268              // per-cluster channel list padded to multiples of 4
#define NGRP  67               // PROWS / 4 channel-groups -> 128-row GEMM tiles
#define MTOT  (PROWS * 32)     // 8576 padded rows (prow*32 + b)

// ------------------------- device scratch -------------------------
__device__ float g_Z[(size_t)MTOT * L_];     // normalized / residual stream
__device__ float g_H[(size_t)MTOT * DFF_];   // hidden activations
__device__ float g_mean[MTOT];
__device__ float g_std[MTOT];
__device__ int   g_chan[PROWS];              // channel id or -1 (pad)
__device__ int   g_clusprow[PROWS];          // cluster of each prow
__device__ int   g_clusgrp[NGRP];            // cluster of each 4-channel group

// ------------------------- f32x2 helpers (Blackwell packed fp32) ---
__device__ __forceinline__ unsigned long long fma2(unsigned long long a,
                                                   unsigned long long b,
                                                   unsigned long long c) {
    unsigned long long d;
    asm("fma.rn.f32x2 %0, %1, %2, %3;" : "=l"(d) : "l"(a), "l"(b), "l"(c));
    return d;
}
__device__ __forceinline__ void unpack2(unsigned long long v, float& lo, float& hi) {
    unsigned int a, b;
    asm("mov.b64 {%0, %1}, %2;" : "=r"(a), "=r"(b) : "l"(v));
    lo = __uint_as_float(a);
    hi = __uint_as_float(b);
}

// ------------------------- cp.async helpers ------------------------
__device__ __forceinline__ void cp_async16(unsigned int dst, const void* src, int bytes) {
    asm volatile("cp.async.ca.shared.global [%0], [%1], 16, %2;\n"
                 :: "r"(dst), "l"(src), "r"(bytes));
}
__device__ __forceinline__ void cp_commit() {
    asm volatile("cp.async.commit_group;\n");
}
__device__ __forceinline__ void cp_wait0() {
    asm volatile("cp.async.wait_group 0;\n");
}

// ------------------------- prep: bucket channels by cluster --------
__global__ void prep_kernel(const int* __restrict__ assign) {
    __shared__ int sa[C_];
    __shared__ int cnt[KC_];
    __shared__ int base[KC_ + 1];
    int t = threadIdx.x;
    if (t < KC_) cnt[t] = 0;
    __syncthreads();
    if (t < C_) {
        int k = assign[t];
        k = min(max(k, 0), KC_ - 1);
        sa[t] = k;
        atomicAdd(&cnt[k], 1);
    }
    __syncthreads();
    if (t == 0) {
        base[0] = 0;
        for (int k = 0; k < KC_; k++) base[k + 1] = base[k] + ((cnt[k] + 3) & ~3);
    }
    __syncthreads();
    for (int p = t; p < PROWS; p += blockDim.x) {
        int kk = 0;
        for (int k = 0; k < KC_; k++) if (p >= base[k + 1]) kk = k + 1;
        if (kk >= KC_) kk = 0;
        g_clusprow[p] = kk;
        g_chan[p] = -1;
    }
    __syncthreads();   // defaults visible before real channel writes
    if (t < C_) {
        int k = sa[t];
        int rank = 0;
        for (int c = 0; c < t; c++) rank += (sa[c] == k);
        g_chan[base[k] + rank] = t;
    }
    if (t < NGRP) {
        int p = t * 4;
        int kk = 0;
        for (int k = 0; k < KC_; k++) if (p >= base[k + 1]) kk = k + 1;
        if (kk >= KC_) kk = 0;
        g_clusgrp[t] = kk;
    }
}

// ------------------------- RevIN normalize (two-pass) --------------
__global__ void revin_kernel(const float* __restrict__ x,
                             const float* __restrict__ rev_w,
                             const float* __restrict__ rev_b) {
    int r = blockIdx.x;             // 0..MTOT-1
    int prow = r >> 5, b = r & 31;
    int c = g_chan[prow];
    int t = threadIdx.x;            // 128 threads
    __shared__ float sx[L_];
    __shared__ float sred[8];
    float* zr = g_Z + (size_t)r * L_;

    if (c < 0) {
        for (int i = t; i < L_; i += 128) zr[i] = 0.f;
        if (t == 0) { g_mean[r] = 0.f; g_std[r] = 1.f; }
        return;
    }
    const float* xr = x + ((size_t)b * C_ + c) * L_;
    float s = 0.f;
    for (int i = t; i < L_; i += 128) { float v = xr[i]; sx[i] = v; s += v; }
    #pragma unroll
    for (int o = 16; o > 0; o >>= 1) s += __shfl_down_sync(0xffffffffu, s, o);
    if ((t & 31) == 0) sred[t >> 5] = s;
    __syncthreads();
    if (t < 32) {
        float v = (t < 4) ? sred[t] : 0.f;
        v += __shfl_down_sync(0xffffffffu, v, 2);
        v += __shfl_down_sync(0xffffffffu, v, 1);
        if (t == 0) sred[4] = v;
    }
    __syncthreads();
    float mean = sred[4] * (1.0f / L_);

    float vs = 0.f;
    for (int i = t; i < L_; i += 128) { float d = sx[i] - mean; vs += d * d; }
    #pragma unroll
    for (int o = 16; o > 0; o >>= 1) vs += __shfl_down_sync(0xffffffffu, vs, o);
    if ((t & 31) == 0) sred[t >> 5] = vs;
    __syncthreads();
    if (t < 32) {
        float v = (t < 4) ? sred[t] : 0.f;
        v += __shfl_down_sync(0xffffffffu, v, 2);
        v += __shfl_down_sync(0xffffffffu, v, 1);
        if (t == 0) sred[5] = v;
    }
    __syncthreads();
    float var  = sred[5] * (1.0f / L_);
    float stdv = sqrtf(var + 1e-5f);
    float w  = rev_w[c], rb = rev_b[c];
    float rs = w / stdv;
    for (int i = t; i < L_; i += 128) zr[i] = (sx[i] - mean) * rs + rb;
    if (t == 0) { g_mean[r] = mean; g_std[r] = stdv; }
}

// ------------------------- fused FFN GEMMs (f32x2 SGEMM) -----------
// 128 threads, 128(M) x 64(N) tiles, KTILE=8.
// A stored in smem PRE-DUPLICATED as f32x2 pairs (no dup MOVs in mainloop).
// B fetched global->smem via cp.async (no register staging).
// FFN1: H = relu(Z @ W1[k,l] + b1)      (K=336,  N=1024)
// FFN2: Z = Z + H @ W2[k,l] + b2        (K=1024, N=336, in-place residual)
template <bool FFN1>
__global__ __launch_bounds__(128, 4) void ffn_gemm(const float* __restrict__ W,
                                                   const float* __restrict__ bias,
                                                   int layer) {
    constexpr int KDIM = FFN1 ? L_ : DFF_;
    constexpr int NDIM = FFN1 ? DFF_ : L_;
    constexpr int LDA  = FFN1 ? L_ : DFF_;
    constexpr int KT   = KDIM / 8;
    const float* A    = FFN1 ? g_Z : g_H;
    float*       Cout = FFN1 ? g_H : g_Z;

    __shared__ __align__(16) float As2[2][8][256];   // duplicated pairs: [kk][2*row{+0,1}]
    __shared__ __align__(16) float Bs[2][8][64];

    const int tid = threadIdx.x;
    const int tx = tid & 7;        // 8 col groups
    const int ty = tid >> 3;       // 16 row groups
    const int m0 = blockIdx.y * 128;
    const int n0 = blockIdx.x * 64;
    const int kc = g_clusgrp[blockIdx.y];
    const float* Wp = W + (size_t)(kc * NL_ + layer) * KDIM * NDIM;
    const float* bp = bias + (size_t)(kc * NL_ + layer) * NDIM;

    // A loader: one row per thread, 8 consecutive k per tile
    const float* Ag = A + (size_t)(m0 + tid) * LDA;
    // B loader: 16B per thread via cp.async
    const int bkr = tid >> 4;             // 8 k-rows
    const int bn  = (tid & 15) * 4;       // 16 x 4 cols = 64
    int brem = NDIM - (n0 + bn);
    const int bbytes = FFN1 ? 16 : (brem >= 4 ? 16 : 0);
    const float* Bg = Wp + (size_t)bkr * NDIM + (bbytes ? (n0 + bn) : 0);

    unsigned int bsAddr[2];
    bsAddr[0] = (unsigned int)__cvta_generic_to_shared(&Bs[0][bkr][bn]);
    bsAddr[1] = (unsigned int)__cvta_generic_to_shared(&Bs[1][bkr][bn]);

    // ---- prologue: stage k-tile 0 ----
    {
        float4 a0 = *(const float4*)(Ag);
        float4 a1 = *(const float4*)(Ag + 4);
        float av[8] = {a0.x, a0.y, a0.z, a0.w, a1.x, a1.y, a1.z, a1.w};
        #pragma unroll
        for (int kk = 0; kk < 8; kk++)
            *(float2*)&As2[0][kk][2 * tid] = make_float2(av[kk], av[kk]);
        cp_async16(bsAddr[0], Bg, bbytes);
        cp_commit();
    }
    cp_wait0();
    __syncthreads();

    unsigned long long acc[8][4];
    #pragma unroll
    for (int r = 0; r < 8; r++)
        #pragma unroll
        for (int j = 0; j < 4; j++) acc[r][j] = 0ULL;

    int buf = 0;
    #pragma unroll 1
    for (int kt = 0; kt < KT; ++kt) {
        const bool more = (kt + 1 < KT);
        float4 aN0, aN1;
        if (more) {
            aN0 = *(const float4*)(Ag + (kt + 1) * 8);
            aN1 = *(const float4*)(Ag + (kt + 1) * 8 + 4);
            cp_async16(bsAddr[buf ^ 1], Bg + (size_t)(kt + 1) * 8 * NDIM, bbytes);
            cp_commit();
        }
        const float* asb = &As2[buf][0][0];
        const float* bsb = &Bs[buf][0][0];
        #pragma unroll
        for (int kk = 0; kk < 8; kk++) {
            ulonglong2 B0 = *(const ulonglong2*)(bsb + kk * 64 + tx * 4);
            ulonglong2 B1 = *(const ulonglong2*)(bsb + kk * 64 + 32 + tx * 4);
            ulonglong2 A0 = *(const ulonglong2*)(asb + kk * 256 + ty * 8);
            ulonglong2 A1 = *(const ulonglong2*)(asb + kk * 256 + ty * 8 + 4);
            ulonglong2 A2 = *(const ulonglong2*)(asb + kk * 256 + 128 + ty * 8);
            ulonglong2 A3 = *(const ulonglong2*)(asb + kk * 256 + 128 + ty * 8 + 4);
            unsigned long long ad[8] = {A0.x, A0.y, A1.x, A1.y, A2.x, A2.y, A3.x, A3.y};
            #pragma unroll
            for (int r = 0; r < 8; r++) {
                acc[r][0] = fma2(ad[r], B0.x, acc[r][0]);
                acc[r][1] = fma2(ad[r], B0.y, acc[r][1]);
                acc[r][2] = fma2(ad[r], B1.x, acc[r][2]);
                acc[r][3] = fma2(ad[r], B1.y, acc[r][3]);
            }
        }
        if (more) {
            float av[8] = {aN0.x, aN0.y, aN0.z, aN0.w, aN1.x, aN1.y, aN1.z, aN1.w};
            int nb = buf ^ 1;
            #pragma unroll
            for (int kk = 0; kk < 8; kk++)
                *(float2*)&As2[nb][kk][2 * tid] = make_float2(av[kk], av[kk]);
            cp_wait0();
            __syncthreads();
            buf = nb;
        }
    }

    // ---- epilogue ----
    bool cval0 = true, cval1 = true;
    if (!FFN1) {
        cval0 = (n0 + tx * 4 + 4 <= NDIM);
        cval1 = (n0 + 32 + tx * 4 + 4 <= NDIM);
    }
    float4 bias0 = make_float4(0.f, 0.f, 0.f, 0.f);
    float4 bias1 = make_float4(0.f, 0.f, 0.f, 0.f);
    if (cval0) bias0 = *(const float4*)&bp[n0 + tx * 4];
    if (cval1) bias1 = *(const float4*)&bp[n0 + 32 + tx * 4];

    #pragma unroll
    for (int r = 0; r < 8; r++) {
        int row = m0 + ((r < 4) ? (ty * 4 + r) : (64 + ty * 4 + (r - 4)));
        float p0x, p0y, p1x, p1y, p2x, p2y, p3x, p3y;
        unpack2(acc[r][0], p0x, p0y);
        unpack2(acc[r][1], p1x, p1y);
        unpack2(acc[r][2], p2x, p2y);
        unpack2(acc[r][3], p3x, p3y);
        if (FFN1) {
            float4 v0 = make_float4(fmaxf(p0x + bias0.x, 0.f), fmaxf(p0y + bias0.y, 0.f),
                                    fmaxf(p1x + bias0.z, 0.f), fmaxf(p1y + bias0.w, 0.f));
            float4 v1 = make_float4(fmaxf(p2x + bias1.x, 0.f), fmaxf(p2y + bias1.y, 0.f),
                                    fmaxf(p3x + bias1.z, 0.f), fmaxf(p3y + bias1.w, 0.f));
            *(float4*)&Cout[(size_t)row * NDIM + n0 + tx * 4] = v0;
            *(float4*)&Cout[(size_t)row * NDIM + n0 + 32 + tx * 4] = v1;
        } else {
            if (cval0) {
                float* cp = &Cout[(size_t)row * NDIM + n0 + tx * 4];
                float4 old = *(const float4*)cp;
                *(float4*)cp = make_float4(old.x + p0x + bias0.x, old.y + p0y + bias0.y,
                                           old.z + p1x + bias0.z, old.w + p1y + bias0.w);
            }
            if (cval1) {
                float* cp = &Cout[(size_t)row * NDIM + n0 + 32 + tx * 4];
                float4 old = *(const float4*)cp;
                *(float4*)cp = make_float4(old.x + p2x + bias1.x, old.y + p2y + bias1.y,
                                           old.z + p3x + bias1.z, old.w + p3y + bias1.w);
            }
        }
    }
}

// ------------------------- head + denorm + transpose ----------------
__global__ void head_kernel(const float* __restrict__ Wh,
                            const float* __restrict__ bh,
                            const float* __restrict__ rev_w,
                            const float* __restrict__ rev_b,
                            float* __restrict__ out) {
    int prow = blockIdx.x;
    int c = g_chan[prow];
    if (c < 0) return;
    int kc = g_clusprow[prow];

    __shared__ __align__(16) float Zs[32][65];
    __shared__ __align__(16) float Ws[64][96];

    int tid = threadIdx.x;       // 256
    int row = tid & 31;          // batch index b
    int cg  = tid >> 5;          // 8 column groups of 12
    float acc[12];
    #pragma unroll
    for (int j = 0; j < 12; j++) acc[j] = 0.f;

    const float* Whk = Wh + (size_t)kc * L_ * O_;
    for (int l0 = 0; l0 < L_; l0 += 64) {
        int lc = min(64, L_ - l0);
        for (int i = tid; i < 32 * 64; i += 256) {
            int rr = i >> 6, ll = i & 63;
            Zs[rr][ll] = (ll < lc) ? g_Z[(size_t)(prow * 32 + rr) * L_ + l0 + ll] : 0.f;
        }
        for (int i = tid; i < 64 * 96; i += 256) {
            int ll = i / 96, o = i - ll * 96;
            Ws[ll][o] = (ll < lc) ? Whk[(size_t)(l0 + ll) * O_ + o] : 0.f;
        }
        __syncthreads();
        #pragma unroll 8
        for (int ll = 0; ll < 64; ll++) {
            float a = Zs[row][ll];
            float4 w0 = *(const float4*)&Ws[ll][cg * 12];
            float4 w1 = *(const float4*)&Ws[ll][cg * 12 + 4];
            float4 w2 = *(const float4*)&Ws[ll][cg * 12 + 8];
            acc[0]  += a * w0.x; acc[1]  += a * w0.y; acc[2]  += a * w0.z; acc[3]  += a * w0.w;
            acc[4]  += a * w1.x; acc[5]  += a * w1.y; acc[6]  += a * w1.z; acc[7]  += a * w1.w;
            acc[8]  += a * w2.x; acc[9]  += a * w2.y; acc[10] += a * w2.z; acc[11] += a * w2.w;
        }
        __syncthreads();
    }

    int rg = prow * 32 + row;
    float mean = g_mean[rg], stdv = g_std[rg];
    float w = rev_w[c], rb = rev_b[c];
    float scale = stdv / w;
    #pragma unroll
    for (int j = 0; j < 12; j++) {
        int o = cg * 12 + j;
        float y = acc[j] + bh[kc * O_ + o];
        out[((size_t)row * O_ + o) * C_ + c] = (y - rb) * scale + mean;
    }
}

// ------------------------- launch ----------------------------------
extern "C" void kernel_launch(void* const* d_in, const int* in_sizes, int n_in,
                              void* d_out, int out_size) {
    const float* x     = (const float*)d_in[0];
    const float* rev_w = (const float*)d_in[1];
    const float* rev_b = (const float*)d_in[2];
    const float* W1    = (const float*)d_in[3];
    const float* b1    = (const float*)d_in[4];
    const float* W2    = (const float*)d_in[5];
    const float* b2    = (const float*)d_in[6];
    const float* Wh    = (const float*)d_in[7];
    const float* bh    = (const float*)d_in[8];
    const int*   assign = (const int*)d_in[9];
    float* out = (float*)d_out;

    prep_kernel<<<1, 256>>>(assign);
    revin_kernel<<<MTOT, 128>>>(x, rev_w, rev_b);
    for (int l = 0; l < NL_; l++) {
        ffn_gemm<true ><<<dim3(DFF_ / 64, NGRP), 128>>>(W1, b1, l);
        ffn_gemm<false><<<dim3((L_ + 63) / 64, NGRP), 128>>>(W2, b2, l);
    }
    head_kernel<<<PROWS, 256>>>(Wh, bh, rev_w, rev_b, out);
}

// round 9
// speedup vs baseline: 1.9319x; 1.9319x over previous
#include <cuda_runtime.h>
#include <cuda_bf16.h>
#include <cstdint>

#define B_    32
#define C_    256
#define L_    336
#define O_    96
#define KC_   4
#define NL_   2
#define DFF_  1024
#define KPAD  384              // L_ padded for k-blocking AND ffn2 n-tiling
#define PROWS 268
#define NGRP  67
#define MTOT  (PROWS * 32)     // 8576 rows (prow*32 + b)

// ------------------------- device scratch -------------------------
__device__ float g_Z[(size_t)MTOT * L_];                 // residual stream fp32
__device__ __nv_bfloat16 g_Zh[(size_t)MTOT * KPAD];      // z split hi
__device__ __nv_bfloat16 g_Zl[(size_t)MTOT * KPAD];      // z split lo
__device__ __nv_bfloat16 g_Hh[(size_t)MTOT * DFF_];      // hidden hi
__device__ __nv_bfloat16 g_Hl[(size_t)MTOT * DFF_];      // hidden lo
__device__ __nv_bfloat16 g_W1T_h[(size_t)KC_ * NL_ * DFF_ * KPAD];  // [kl][n][k]
__device__ __nv_bfloat16 g_W1T_l[(size_t)KC_ * NL_ * DFF_ * KPAD];
__device__ __nv_bfloat16 g_W2T_h[(size_t)KC_ * NL_ * KPAD * DFF_];  // [kl][n(384)][d]
__device__ __nv_bfloat16 g_W2T_l[(size_t)KC_ * NL_ * KPAD * DFF_];
__device__ float g_mean[MTOT];
__device__ float g_std[MTOT];
__device__ int   g_chan[PROWS];
__device__ int   g_clusprow[PROWS];
__device__ int   g_clusgrp[NGRP];

// ------------------------- PTX helpers -----------------------------
__device__ __forceinline__ void ldsm4(uint32_t* r, uint32_t addr) {
    asm volatile("ldmatrix.sync.aligned.m8n8.x4.shared.b16 {%0,%1,%2,%3}, [%4];"
                 : "=r"(r[0]), "=r"(r[1]), "=r"(r[2]), "=r"(r[3]) : "r"(addr));
}
__device__ __forceinline__ void mma16816(float* d, const uint32_t* a,
                                         uint32_t b0, uint32_t b1) {
    asm volatile("mma.sync.aligned.m16n8k16.row.col.f32.bf16.bf16.f32 "
                 "{%0,%1,%2,%3}, {%4,%5,%6,%7}, {%8,%9}, {%0,%1,%2,%3};"
                 : "+f"(d[0]), "+f"(d[1]), "+f"(d[2]), "+f"(d[3])
                 : "r"(a[0]), "r"(a[1]), "r"(a[2]), "r"(a[3]), "r"(b0), "r"(b1));
}
__device__ __forceinline__ void cp_async16(uint32_t dst, const void* src) {
    asm volatile("cp.async.cg.shared.global [%0], [%1], 16;" :: "r"(dst), "l"(src));
}
__device__ __forceinline__ void cp_commit() { asm volatile("cp.async.commit_group;"); }
template <int N> __device__ __forceinline__ void cp_wait_n() {
    asm volatile("cp.async.wait_group %0;" :: "n"(N));
}
__device__ __forceinline__ void split_bf16(float y, __nv_bfloat16& h, __nv_bfloat16& l) {
    h = __float2bfloat16(y);
    l = __float2bfloat16(y - __bfloat162float(h));
}

// ------------------------- prep: bucket channels by cluster --------
__global__ void prep_kernel(const int* __restrict__ assign) {
    __shared__ int sa[C_];
    __shared__ int cnt[KC_];
    __shared__ int base[KC_ + 1];
    int t = threadIdx.x;
    if (t < KC_) cnt[t] = 0;
    __syncthreads();
    if (t < C_) {
        int k = assign[t];
        k = min(max(k, 0), KC_ - 1);
        sa[t] = k;
        atomicAdd(&cnt[k], 1);
    }
    __syncthreads();
    if (t == 0) {
        base[0] = 0;
        for (int k = 0; k < KC_; k++) base[k + 1] = base[k] + ((cnt[k] + 3) & ~3);
    }
    __syncthreads();
    for (int p = t; p < PROWS; p += blockDim.x) {
        int kk = 0;
        for (int k = 0; k < KC_; k++) if (p >= base[k + 1]) kk = k + 1;
        if (kk >= KC_) kk = 0;
        g_clusprow[p] = kk;
        g_chan[p] = -1;
    }
    __syncthreads();
    if (t < C_) {
        int k = sa[t];
        int rank = 0;
        for (int c = 0; c < t; c++) rank += (sa[c] == k);
        g_chan[base[k] + rank] = t;
    }
    if (t < NGRP) {
        int p = t * 4;
        int kk = 0;
        for (int k = 0; k < KC_; k++) if (p >= base[k + 1]) kk = k + 1;
        if (kk >= KC_) kk = 0;
        g_clusgrp[t] = kk;
    }
}

// ------------------------- weight transpose + bf16 split -----------
// W1 [kl][336][1024] -> W1T_h/l [kl][1024][384]
__global__ void convW1_kernel(const float* __restrict__ W1) {
    __shared__ float tile[32][33];
    int n0 = blockIdx.x * 32, k0 = blockIdx.y * 32, kl = blockIdx.z;
    int tx = threadIdx.x, ty = threadIdx.y;
    const float* src = W1 + (size_t)kl * L_ * DFF_;
    for (int r = ty; r < 32; r += 8) {
        int k = k0 + r;
        tile[r][tx] = (k < L_) ? src[(size_t)k * DFF_ + n0 + tx] : 0.f;
    }
    __syncthreads();
    for (int r = ty; r < 32; r += 8) {
        int n = n0 + r, k = k0 + tx;
        float v = tile[tx][r];
        __nv_bfloat16 h, l; split_bf16(v, h, l);
        size_t o = ((size_t)kl * DFF_ + n) * KPAD + k;
        g_W1T_h[o] = h; g_W1T_l[o] = l;
    }
}

// W2 [kl][1024][336] -> W2T_h/l [kl][384][1024]
__global__ void convW2_kernel(const float* __restrict__ W2) {
    __shared__ float tile[32][33];
    int d0 = blockIdx.x * 32, n0 = blockIdx.y * 32, kl = blockIdx.z;
    int tx = threadIdx.x, ty = threadIdx.y;
    const float* src = W2 + (size_t)kl * DFF_ * L_;
    for (int r = ty; r < 32; r += 8) {
        int n = n0 + tx;
        tile[r][tx] = (n < L_) ? src[(size_t)(d0 + r) * L_ + n] : 0.f;
    }
    __syncthreads();
    for (int r = ty; r < 32; r += 8) {
        int n = n0 + r, d = d0 + tx;
        float v = tile[tx][r];
        __nv_bfloat16 h, l; split_bf16(v, h, l);
        size_t o = ((size_t)kl * KPAD + n) * DFF_ + d;
        g_W2T_h[o] = h; g_W2T_l[o] = l;
    }
}

// ------------------------- RevIN normalize -------------------------
__global__ void revin_kernel(const float* __restrict__ x,
                             const float* __restrict__ rev_w,
                             const float* __restrict__ rev_b) {
    int r = blockIdx.x;
    int prow = r >> 5, b = r & 31;
    int c = g_chan[prow];
    int t = threadIdx.x;            // 128
    __shared__ float sx[L_];
    __shared__ float sred[8];
    float* zr = g_Z + (size_t)r * L_;
    __nv_bfloat16* zh = g_Zh + (size_t)r * KPAD;
    __nv_bfloat16* zl = g_Zl + (size_t)r * KPAD;

    if (c < 0) {
        for (int i = t; i < L_; i += 128) zr[i] = 0.f;
        for (int i = t; i < KPAD; i += 128) { zh[i] = __float2bfloat16(0.f); zl[i] = __float2bfloat16(0.f); }
        if (t == 0) { g_mean[r] = 0.f; g_std[r] = 1.f; }
        return;
    }
    const float* xr = x + ((size_t)b * C_ + c) * L_;
    float s = 0.f;
    for (int i = t; i < L_; i += 128) { float v = xr[i]; sx[i] = v; s += v; }
    #pragma unroll
    for (int o = 16; o > 0; o >>= 1) s += __shfl_down_sync(0xffffffffu, s, o);
    if ((t & 31) == 0) sred[t >> 5] = s;
    __syncthreads();
    if (t < 32) {
        float v = (t < 4) ? sred[t] : 0.f;
        v += __shfl_down_sync(0xffffffffu, v, 2);
        v += __shfl_down_sync(0xffffffffu, v, 1);
        if (t == 0) sred[4] = v;
    }
    __syncthreads();
    float mean = sred[4] * (1.0f / L_);

    float vs = 0.f;
    for (int i = t; i < L_; i += 128) { float d = sx[i] - mean; vs += d * d; }
    #pragma unroll
    for (int o = 16; o > 0; o >>= 1) vs += __shfl_down_sync(0xffffffffu, vs, o);
    if ((t & 31) == 0) sred[t >> 5] = vs;
    __syncthreads();
    if (t < 32) {
        float v = (t < 4) ? sred[t] : 0.f;
        v += __shfl_down_sync(0xffffffffu, v, 2);
        v += __shfl_down_sync(0xffffffffu, v, 1);
        if (t == 0) sred[5] = v;
    }
    __syncthreads();
    float var  = sred[5] * (1.0f / L_);
    float stdv = sqrtf(var + 1e-5f);
    float w  = rev_w[c], rb = rev_b[c];
    float rs = w / stdv;
    for (int i = t; i < L_; i += 128) {
        float v = (sx[i] - mean) * rs + rb;
        zr[i] = v;
        __nv_bfloat16 h, l; split_bf16(v, h, l);
        zh[i] = h; zl[i] = l;
    }
    for (int i = L_ + t; i < KPAD; i += 128) { zh[i] = __float2bfloat16(0.f); zl[i] = __float2bfloat16(0.f); }
    if (t == 0) { g_mean[r] = mean; g_std[r] = stdv; }
}

// ------------------------- HMMA FFN GEMMs --------------------------
// D[128,128] = A[128,K] @ W[K,128] via 3-term bf16 split on mma.sync.
// 256 thr = 8 warps (4m x 2n), warp tile 32x64, k-block 32, double buffer.
// smem per buffer: Ah, Al, Bh, Bl tiles, each 128 rows x 32 bf16, row stride
// 40 bf16 (80 B) -> conflict-free ldmatrix (80*i mod 128 covers all banks).
#define TILE_B   10240                 // 128*80
#define BUF_B    (4 * TILE_B)          // 40960
#define FFN_SMEM (2 * BUF_B)           // 81920

template <bool IS1>
__global__ __launch_bounds__(256, 2) void ffn_mma(const float* __restrict__ bias, int layer) {
    constexpr int NB   = IS1 ? (KPAD / 32) : (DFF_ / 32);   // 12 : 32
    constexpr int ASTR = IS1 ? KPAD : DFF_;
    constexpr int BSTR = IS1 ? KPAD : DFF_;

    extern __shared__ char smem[];
    uint32_t sb = (uint32_t)__cvta_generic_to_shared(smem);
    const int tid  = threadIdx.x;
    const int wid  = tid >> 5, lane = tid & 31;
    const int warp_m = wid & 3;        // 0..3 -> m offset 32*warp_m
    const int warp_n = wid >> 2;       // 0..1 -> n offset 64*warp_n

    const int n0 = blockIdx.x * 128;
    const int m0 = blockIdx.y * 128;
    const int kl = g_clusgrp[blockIdx.y] * NL_ + layer;

    const __nv_bfloat16* Ah0 = (IS1 ? g_Zh : g_Hh) + (size_t)m0 * ASTR;
    const __nv_bfloat16* Al0 = (IS1 ? g_Zl : g_Hl) + (size_t)m0 * ASTR;
    const __nv_bfloat16* Bh0 = (IS1 ? g_W1T_h : g_W2T_h) +
                               ((size_t)kl * (IS1 ? DFF_ : KPAD) + n0) * BSTR;
    const __nv_bfloat16* Bl0 = (IS1 ? g_W1T_l : g_W2T_l) +
                               ((size_t)kl * (IS1 ? DFF_ : KPAD) + n0) * BSTR;
    const float* bp = bias + (size_t)kl * (IS1 ? DFF_ : L_);

    // chunk mapping: 512 chunks of 16B per tile matrix, 2 per thread
    const int ch0 = tid, ch1 = tid + 256;
    const int r0c = ch0 >> 2, c0c = ch0 & 3;
    const int r1c = ch1 >> 2, c1c = ch1 & 3;

    auto stage = [&](int buf, int kb) {
        uint32_t base = sb + buf * BUF_B;
        uint32_t d0 = base + (uint32_t)(r0c * 80 + c0c * 16);
        uint32_t d1 = base + (uint32_t)(r1c * 80 + c1c * 16);
        size_t s0 = (size_t)r0c * ASTR + kb * 32 + c0c * 8;
        size_t s1 = (size_t)r1c * ASTR + kb * 32 + c1c * 8;
        size_t t0 = (size_t)r0c * BSTR + kb * 32 + c0c * 8;
        size_t t1 = (size_t)r1c * BSTR + kb * 32 + c1c * 8;
        cp_async16(d0,              Ah0 + s0);
        cp_async16(d1,              Ah0 + s1);
        cp_async16(d0 + TILE_B,     Al0 + s0);
        cp_async16(d1 + TILE_B,     Al0 + s1);
        cp_async16(d0 + 2 * TILE_B, Bh0 + t0);
        cp_async16(d1 + 2 * TILE_B, Bh0 + t1);
        cp_async16(d0 + 3 * TILE_B, Bl0 + t0);
        cp_async16(d1 + 3 * TILE_B, Bl0 + t1);
        cp_commit();
    };

    float acc[2][8][4];
    #pragma unroll
    for (int mt = 0; mt < 2; mt++)
        #pragma unroll
        for (int nt = 0; nt < 8; nt++)
            #pragma unroll
            for (int j = 0; j < 4; j++) acc[mt][nt][j] = 0.f;

    stage(0, 0);
    stage(1, 1);

    #pragma unroll 1
    for (int kb = 0; kb < NB; kb++) {
        if (kb + 1 < NB) cp_wait_n<1>(); else cp_wait_n<0>();
        __syncthreads();
        uint32_t bufb = sb + (kb & 1) * BUF_B;

        #pragma unroll
        for (int ks = 0; ks < 2; ks++) {
            uint32_t ah[2][4], al[2][4];
            #pragma unroll
            for (int mt = 0; mt < 2; mt++) {
                uint32_t aoff = (uint32_t)((warp_m * 32 + mt * 16 + (lane & 15)) * 80 +
                                           ks * 32 + ((lane >> 4) * 16));
                ldsm4(ah[mt], bufb + aoff);
                ldsm4(al[mt], bufb + TILE_B + aoff);
            }
            #pragma unroll
            for (int p = 0; p < 4; p++) {
                int g = lane >> 3;
                uint32_t boff = (uint32_t)((warp_n * 64 + (2 * p + (g >> 1)) * 8 + (lane & 7)) * 80 +
                                           ks * 32 + (g & 1) * 16);
                uint32_t bh4[4], bl4[4];
                ldsm4(bh4, bufb + 2 * TILE_B + boff);
                ldsm4(bl4, bufb + 3 * TILE_B + boff);
                #pragma unroll
                for (int half = 0; half < 2; half++) {
                    int nt = 2 * p + half;
                    uint32_t bh0 = bh4[2 * half], bh1 = bh4[2 * half + 1];
                    uint32_t bl0 = bl4[2 * half], bl1 = bl4[2 * half + 1];
                    #pragma unroll
                    for (int mt = 0; mt < 2; mt++) {
                        mma16816(acc[mt][nt], ah[mt], bh0, bh1);   // hi*hi
                        mma16816(acc[mt][nt], ah[mt], bl0, bl1);   // hi*lo
                        mma16816(acc[mt][nt], al[mt], bh0, bh1);   // lo*hi
                    }
                }
            }
        }
        __syncthreads();
        if (kb + 2 < NB) stage(kb & 1, kb + 2);
    }

    // ---- epilogue ----
    const int gq = lane >> 2, tq = lane & 3;
    #pragma unroll
    for (int mt = 0; mt < 2; mt++) {
        int rA = m0 + warp_m * 32 + mt * 16 + gq;
        int rB = rA + 8;
        #pragma unroll
        for (int nt = 0; nt < 8; nt++) {
            int col = n0 + warp_n * 64 + nt * 8 + tq * 2;
            if (IS1) {
                float2 bv = *(const float2*)&bp[col];
                float y0 = fmaxf(acc[mt][nt][0] + bv.x, 0.f);
                float y1 = fmaxf(acc[mt][nt][1] + bv.y, 0.f);
                float y2 = fmaxf(acc[mt][nt][2] + bv.x, 0.f);
                float y3 = fmaxf(acc[mt][nt][3] + bv.y, 0.f);
                __nv_bfloat16 h0, l0, h1, l1, h2, l2, h3, l3;
                split_bf16(y0, h0, l0); split_bf16(y1, h1, l1);
                split_bf16(y2, h2, l2); split_bf16(y3, h3, l3);
                __nv_bfloat162 pha; pha.x = h0; pha.y = h1;
                __nv_bfloat162 pla; pla.x = l0; pla.y = l1;
                __nv_bfloat162 phb; phb.x = h2; phb.y = h3;
                __nv_bfloat162 plb; plb.x = l2; plb.y = l3;
                *(__nv_bfloat162*)(g_Hh + (size_t)rA * DFF_ + col) = pha;
                *(__nv_bfloat162*)(g_Hl + (size_t)rA * DFF_ + col) = pla;
                *(__nv_bfloat162*)(g_Hh + (size_t)rB * DFF_ + col) = phb;
                *(__nv_bfloat162*)(g_Hl + (size_t)rB * DFF_ + col) = plb;
            } else {
                if (col < L_) {
                    float2 bv = *(const float2*)&bp[col];
                    float2* zpA = (float2*)(g_Z + (size_t)rA * L_ + col);
                    float2* zpB = (float2*)(g_Z + (size_t)rB * L_ + col);
                    float2 zA = *zpA, zB = *zpB;
                    float z0 = zA.x + acc[mt][nt][0] + bv.x;
                    float z1 = zA.y + acc[mt][nt][1] + bv.y;
                    float z2 = zB.x + acc[mt][nt][2] + bv.x;
                    float z3 = zB.y + acc[mt][nt][3] + bv.y;
                    *zpA = make_float2(z0, z1);
                    *zpB = make_float2(z2, z3);
                    __nv_bfloat16 h0, l0, h1, l1, h2, l2, h3, l3;
                    split_bf16(z0, h0, l0); split_bf16(z1, h1, l1);
                    split_bf16(z2, h2, l2); split_bf16(z3, h3, l3);
                    __nv_bfloat162 pha; pha.x = h0; pha.y = h1;
                    __nv_bfloat162 pla; pla.x = l0; pla.y = l1;
                    __nv_bfloat162 phb; phb.x = h2; phb.y = h3;
                    __nv_bfloat162 plb; plb.x = l2; plb.y = l3;
                    *(__nv_bfloat162*)(g_Zh + (size_t)rA * KPAD + col) = pha;
                    *(__nv_bfloat162*)(g_Zl + (size_t)rA * KPAD + col) = pla;
                    *(__nv_bfloat162*)(g_Zh + (size_t)rB * KPAD + col) = phb;
                    *(__nv_bfloat162*)(g_Zl + (size_t)rB * KPAD + col) = plb;
                }
            }
        }
    }
}

// ------------------------- head + denorm + transpose ----------------
__global__ void head_kernel(const float* __restrict__ Wh,
                            const float* __restrict__ bh,
                            const float* __restrict__ rev_w,
                            const float* __restrict__ rev_b,
                            float* __restrict__ out) {
    int prow = blockIdx.x;
    int c = g_chan[prow];
    if (c < 0) return;
    int kc = g_clusprow[prow];

    __shared__ __align__(16) float Zs[32][65];
    __shared__ __align__(16) float Ws[64][96];

    int tid = threadIdx.x;       // 256
    int row = tid & 31;
    int cg  = tid >> 5;
    float acc[12];
    #pragma unroll
    for (int j = 0; j < 12; j++) acc[j] = 0.f;

    const float* Whk = Wh + (size_t)kc * L_ * O_;
    for (int l0 = 0; l0 < L_; l0 += 64) {
        int lc = min(64, L_ - l0);
        for (int i = tid; i < 32 * 64; i += 256) {
            int rr = i >> 6, ll = i & 63;
            Zs[rr][ll] = (ll < lc) ? g_Z[(size_t)(prow * 32 + rr) * L_ + l0 + ll] : 0.f;
        }
        for (int i = tid; i < 64 * 96; i += 256) {
            int ll = i / 96, o = i - ll * 96;
            Ws[ll][o] = (ll < lc) ? Whk[(size_t)(l0 + ll) * O_ + o] : 0.f;
        }
        __syncthreads();
        #pragma unroll 8
        for (int ll = 0; ll < 64; ll++) {
            float a = Zs[row][ll];
            float4 w0 = *(const float4*)&Ws[ll][cg * 12];
            float4 w1 = *(const float4*)&Ws[ll][cg * 12 + 4];
            float4 w2 = *(const float4*)&Ws[ll][cg * 12 + 8];
            acc[0]  += a * w0.x; acc[1]  += a * w0.y; acc[2]  += a * w0.z; acc[3]  += a * w0.w;
            acc[4]  += a * w1.x; acc[5]  += a * w1.y; acc[6]  += a * w1.z; acc[7]  += a * w1.w;
            acc[8]  += a * w2.x; acc[9]  += a * w2.y; acc[10] += a * w2.z; acc[11] += a * w2.w;
        }
        __syncthreads();
    }

    int rg = prow * 32 + row;
    float mean = g_mean[rg], stdv = g_std[rg];
    float w = rev_w[c], rb = rev_b[c];
    float scale = stdv / w;
    #pragma unroll
    for (int j = 0; j < 12; j++) {
        int o = cg * 12 + j;
        float y = acc[j] + bh[kc * O_ + o];
        out[((size_t)row * O_ + o) * C_ + c] = (y - rb) * scale + mean;
    }
}

// ------------------------- launch ----------------------------------
extern "C" void kernel_launch(void* const* d_in, const int* in_sizes, int n_in,
                              void* d_out, int out_size) {
    const float* x     = (const float*)d_in[0];
    const float* rev_w = (const float*)d_in[1];
    const float* rev_b = (const float*)d_in[2];
    const float* W1    = (const float*)d_in[3];
    const float* b1    = (const float*)d_in[4];
    const float* W2    = (const float*)d_in[5];
    const float* b2    = (const float*)d_in[6];
    const float* Wh    = (const float*)d_in[7];
    const float* bh    = (const float*)d_in[8];
    const int*   assign = (const int*)d_in[9];
    float* out = (float*)d_out;

    cudaFuncSetAttribute(ffn_mma<true>,  cudaFuncAttributeMaxDynamicSharedMemorySize, FFN_SMEM);
    cudaFuncSetAttribute(ffn_mma<false>, cudaFuncAttributeMaxDynamicSharedMemorySize, FFN_SMEM);

    prep_kernel<<<1, 256>>>(assign);
    convW1_kernel<<<dim3(DFF_ / 32, KPAD / 32, KC_ * NL_), dim3(32, 8)>>>(W1);
    convW2_kernel<<<dim3(DFF_ / 32, KPAD / 32, KC_ * NL_), dim3(32, 8)>>>(W2);
    revin_kernel<<<MTOT, 128>>>(x, rev_w, rev_b);
    for (int l = 0; l < NL_; l++) {
        ffn_mma<true ><<<dim3(DFF_ / 128, NGRP), 256, FFN_SMEM>>>(b1, l);
        ffn_mma<false><<<dim3(KPAD / 128, NGRP), 256, FFN_SMEM>>>(b2, l);
    }
    head_kernel<<<PROWS, 256>>>(Wh, bh, rev_w, rev_b, out);
}

// round 10
// speedup vs baseline: 1.9774x; 1.0235x over previous
#include <cuda_runtime.h>
#include <cuda_bf16.h>
#include <cstdint>

#define B_    32
#define C_    256
#define L_    336
#define O_    96
#define KC_   4
#define NL_   2
#define DFF_  1024
#define KPAD  384              // L_ padded for k-blocking AND ffn2 n-tiling
#define PROWS 268
#define NGRP  67
#define MTOT  (PROWS * 32)     // 8576 rows (prow*32 + b)

// ------------------------- device scratch -------------------------
__device__ float g_Z[(size_t)MTOT * L_];                 // residual stream fp32
__device__ __nv_bfloat16 g_Zh[(size_t)MTOT * KPAD];      // z split hi
__device__ __nv_bfloat16 g_Zl[(size_t)MTOT * KPAD];      // z split lo
__device__ __nv_bfloat16 g_Hh[(size_t)MTOT * DFF_];      // hidden hi
__device__ __nv_bfloat16 g_Hl[(size_t)MTOT * DFF_];      // hidden lo
__device__ __nv_bfloat16 g_W1T_h[(size_t)KC_ * NL_ * DFF_ * KPAD];  // [kl][n][k]
__device__ __nv_bfloat16 g_W1T_l[(size_t)KC_ * NL_ * DFF_ * KPAD];
__device__ __nv_bfloat16 g_W2T_h[(size_t)KC_ * NL_ * KPAD * DFF_];  // [kl][n(384)][d]
__device__ __nv_bfloat16 g_W2T_l[(size_t)KC_ * NL_ * KPAD * DFF_];
__device__ float g_mean[MTOT];
__device__ float g_std[MTOT];
__device__ int   g_chan[PROWS];
__device__ int   g_clusprow[PROWS];
__device__ int   g_clusgrp[NGRP];

// ------------------------- PTX helpers -----------------------------
__device__ __forceinline__ void ldsm4(uint32_t* r, uint32_t addr) {
    asm volatile("ldmatrix.sync.aligned.m8n8.x4.shared.b16 {%0,%1,%2,%3}, [%4];"
                 : "=r"(r[0]), "=r"(r[1]), "=r"(r[2]), "=r"(r[3]) : "r"(addr));
}
__device__ __forceinline__ void mma16816(float* d, const uint32_t* a,
                                         uint32_t b0, uint32_t b1) {
    asm volatile("mma.sync.aligned.m16n8k16.row.col.f32.bf16.bf16.f32 "
                 "{%0,%1,%2,%3}, {%4,%5,%6,%7}, {%8,%9}, {%0,%1,%2,%3};"
                 : "+f"(d[0]), "+f"(d[1]), "+f"(d[2]), "+f"(d[3])
                 : "r"(a[0]), "r"(a[1]), "r"(a[2]), "r"(a[3]), "r"(b0), "r"(b1));
}
__device__ __forceinline__ void cp_async16(uint32_t dst, const void* src) {
    asm volatile("cp.async.cg.shared.global [%0], [%1], 16;" :: "r"(dst), "l"(src));
}
__device__ __forceinline__ void cp_commit() { asm volatile("cp.async.commit_group;"); }
template <int N> __device__ __forceinline__ void cp_wait_n() {
    asm volatile("cp.async.wait_group %0;" :: "n"(N));
}
__device__ __forceinline__ void split_bf16(float y, __nv_bfloat16& h, __nv_bfloat16& l) {
    h = __float2bfloat16(y);
    l = __float2bfloat16(y - __bfloat162float(h));
}

// ------------------------- prep: bucket channels by cluster --------
__global__ void prep_kernel(const int* __restrict__ assign) {
    __shared__ int sa[C_];
    __shared__ int cnt[KC_];
    __shared__ int base[KC_ + 1];
    int t = threadIdx.x;
    if (t < KC_) cnt[t] = 0;
    __syncthreads();
    if (t < C_) {
        int k = assign[t];
        k = min(max(k, 0), KC_ - 1);
        sa[t] = k;
        atomicAdd(&cnt[k], 1);
    }
    __syncthreads();
    if (t == 0) {
        base[0] = 0;
        for (int k = 0; k < KC_; k++) base[k + 1] = base[k] + ((cnt[k] + 3) & ~3);
    }
    __syncthreads();
    for (int p = t; p < PROWS; p += blockDim.x) {
        int kk = 0;
        for (int k = 0; k < KC_; k++) if (p >= base[k + 1]) kk = k + 1;
        if (kk >= KC_) kk = 0;
        g_clusprow[p] = kk;
        g_chan[p] = -1;
    }
    __syncthreads();
    if (t < C_) {
        int k = sa[t];
        int rank = 0;
        for (int c = 0; c < t; c++) rank += (sa[c] == k);
        g_chan[base[k] + rank] = t;
    }
    if (t < NGRP) {
        int p = t * 4;
        int kk = 0;
        for (int k = 0; k < KC_; k++) if (p >= base[k + 1]) kk = k + 1;
        if (kk >= KC_) kk = 0;
        g_clusgrp[t] = kk;
    }
}

// ------------------------- weight transpose + bf16 split -----------
// W1 [kl][336][1024] -> W1T_h/l [kl][1024][384]
__global__ void convW1_kernel(const float* __restrict__ W1) {
    __shared__ float tile[32][33];
    int n0 = blockIdx.x * 32, k0 = blockIdx.y * 32, kl = blockIdx.z;
    int tx = threadIdx.x, ty = threadIdx.y;
    const float* src = W1 + (size_t)kl * L_ * DFF_;
    for (int r = ty; r < 32; r += 8) {
        int k = k0 + r;
        tile[r][tx] = (k < L_) ? src[(size_t)k * DFF_ + n0 + tx] : 0.f;
    }
    __syncthreads();
    for (int r = ty; r < 32; r += 8) {
        int n = n0 + r, k = k0 + tx;
        float v = tile[tx][r];
        __nv_bfloat16 h, l; split_bf16(v, h, l);
        size_t o = ((size_t)kl * DFF_ + n) * KPAD + k;
        g_W1T_h[o] = h; g_W1T_l[o] = l;
    }
}

// W2 [kl][1024][336] -> W2T_h/l [kl][384][1024]
__global__ void convW2_kernel(const float* __restrict__ W2) {
    __shared__ float tile[32][33];
    int d0 = blockIdx.x * 32, n0 = blockIdx.y * 32, kl = blockIdx.z;
    int tx = threadIdx.x, ty = threadIdx.y;
    const float* src = W2 + (size_t)kl * DFF_ * L_;
    for (int r = ty; r < 32; r += 8) {
        int n = n0 + tx;
        tile[r][tx] = (n < L_) ? src[(size_t)(d0 + r) * L_ + n] : 0.f;
    }
    __syncthreads();
    for (int r = ty; r < 32; r += 8) {
        int n = n0 + r, d = d0 + tx;
        float v = tile[tx][r];
        __nv_bfloat16 h, l; split_bf16(v, h, l);
        size_t o = ((size_t)kl * KPAD + n) * DFF_ + d;
        g_W2T_h[o] = h; g_W2T_l[o] = l;
    }
}

// ------------------------- RevIN normalize -------------------------
__global__ void revin_kernel(const float* __restrict__ x,
                             const float* __restrict__ rev_w,
                             const float* __restrict__ rev_b) {
    int r = blockIdx.x;
    int prow = r >> 5, b = r & 31;
    int c = g_chan[prow];
    int t = threadIdx.x;            // 128
    __shared__ float sx[L_];
    __shared__ float sred[8];
    float* zr = g_Z + (size_t)r * L_;
    __nv_bfloat16* zh = g_Zh + (size_t)r * KPAD;
    __nv_bfloat16* zl = g_Zl + (size_t)r * KPAD;

    if (c < 0) {
        for (int i = t; i < L_; i += 128) zr[i] = 0.f;
        for (int i = t; i < KPAD; i += 128) { zh[i] = __float2bfloat16(0.f); zl[i] = __float2bfloat16(0.f); }
        if (t == 0) { g_mean[r] = 0.f; g_std[r] = 1.f; }
        return;
    }
    const float* xr = x + ((size_t)b * C_ + c) * L_;
    float s = 0.f;
    for (int i = t; i < L_; i += 128) { float v = xr[i]; sx[i] = v; s += v; }
    #pragma unroll
    for (int o = 16; o > 0; o >>= 1) s += __shfl_down_sync(0xffffffffu, s, o);
    if ((t & 31) == 0) sred[t >> 5] = s;
    __syncthreads();
    if (t < 32) {
        float v = (t < 4) ? sred[t] : 0.f;
        v += __shfl_down_sync(0xffffffffu, v, 2);
        v += __shfl_down_sync(0xffffffffu, v, 1);
        if (t == 0) sred[4] = v;
    }
    __syncthreads();
    float mean = sred[4] * (1.0f / L_);

    float vs = 0.f;
    for (int i = t; i < L_; i += 128) { float d = sx[i] - mean; vs += d * d; }
    #pragma unroll
    for (int o = 16; o > 0; o >>= 1) vs += __shfl_down_sync(0xffffffffu, vs, o);
    if ((t & 31) == 0) sred[t >> 5] = vs;
    __syncthreads();
    if (t < 32) {
        float v = (t < 4) ? sred[t] : 0.f;
        v += __shfl_down_sync(0xffffffffu, v, 2);
        v += __shfl_down_sync(0xffffffffu, v, 1);
        if (t == 0) sred[5] = v;
    }
    __syncthreads();
    float var  = sred[5] * (1.0f / L_);
    float stdv = sqrtf(var + 1e-5f);
    float w  = rev_w[c], rb = rev_b[c];
    float rs = w / stdv;
    for (int i = t; i < L_; i += 128) {
        float v = (sx[i] - mean) * rs + rb;
        zr[i] = v;
        __nv_bfloat16 h, l; split_bf16(v, h, l);
        zh[i] = h; zl[i] = l;
    }
    for (int i = L_ + t; i < KPAD; i += 128) { zh[i] = __float2bfloat16(0.f); zl[i] = __float2bfloat16(0.f); }
    if (t == 0) { g_mean[r] = mean; g_std[r] = stdv; }
}

// ------------------------- HMMA FFN GEMMs --------------------------
// D[128,128] = A[128,K] @ W[K,128] via 3-term bf16 split on mma.sync.
// 256 thr = 8 warps (4m x 2n), warp tile 32x64, k-block 32, double buffer.
// Mainloop issues MMAs TERM-MAJOR over p-pairs so each accumulator is
// reused only every 8 MMAs (hides HMMA RAW latency; was distance-1).
#define TILE_B   10240                 // 128*80
#define BUF_B    (4 * TILE_B)          // 40960
#define FFN_SMEM (2 * BUF_B)           // 81920

template <bool IS1>
__global__ __launch_bounds__(256, 2) void ffn_mma(const float* __restrict__ bias, int layer) {
    // FFN1: K=336 -> 11 k-blocks of 32 (352 >= 336; rows 336..351 are zero-padded)
    constexpr int NB   = IS1 ? 11 : (DFF_ / 32);   // 11 : 32
    constexpr int ASTR = IS1 ? KPAD : DFF_;
    constexpr int BSTR = IS1 ? KPAD : DFF_;

    extern __shared__ char smem[];
    uint32_t sb = (uint32_t)__cvta_generic_to_shared(smem);
    const int tid  = threadIdx.x;
    const int wid  = tid >> 5, lane = tid & 31;
    const int warp_m = wid & 3;        // 0..3 -> m offset 32*warp_m
    const int warp_n = wid >> 2;       // 0..1 -> n offset 64*warp_n

    const int n0 = blockIdx.x * 128;
    const int m0 = blockIdx.y * 128;
    const int kl = g_clusgrp[blockIdx.y] * NL_ + layer;

    const __nv_bfloat16* Ah0 = (IS1 ? g_Zh : g_Hh) + (size_t)m0 * ASTR;
    const __nv_bfloat16* Al0 = (IS1 ? g_Zl : g_Hl) + (size_t)m0 * ASTR;
    const __nv_bfloat16* Bh0 = (IS1 ? g_W1T_h : g_W2T_h) +
                               ((size_t)kl * (IS1 ? DFF_ : KPAD) + n0) * BSTR;
    const __nv_bfloat16* Bl0 = (IS1 ? g_W1T_l : g_W2T_l) +
                               ((size_t)kl * (IS1 ? DFF_ : KPAD) + n0) * BSTR;
    const float* bp = bias + (size_t)kl * (IS1 ? DFF_ : L_);

    // chunk mapping: 512 chunks of 16B per tile matrix, 2 per thread
    const int ch0 = tid, ch1 = tid + 256;
    const int r0c = ch0 >> 2, c0c = ch0 & 3;
    const int r1c = ch1 >> 2, c1c = ch1 & 3;

    auto stage = [&](int buf, int kb) {
        uint32_t base = sb + buf * BUF_B;
        uint32_t d0 = base + (uint32_t)(r0c * 80 + c0c * 16);
        uint32_t d1 = base + (uint32_t)(r1c * 80 + c1c * 16);
        size_t s0 = (size_t)r0c * ASTR + kb * 32 + c0c * 8;
        size_t s1 = (size_t)r1c * ASTR + kb * 32 + c1c * 8;
        size_t t0 = (size_t)r0c * BSTR + kb * 32 + c0c * 8;
        size_t t1 = (size_t)r1c * BSTR + kb * 32 + c1c * 8;
        cp_async16(d0,              Ah0 + s0);
        cp_async16(d1,              Ah0 + s1);
        cp_async16(d0 + TILE_B,     Al0 + s0);
        cp_async16(d1 + TILE_B,     Al0 + s1);
        cp_async16(d0 + 2 * TILE_B, Bh0 + t0);
        cp_async16(d1 + 2 * TILE_B, Bh0 + t1);
        cp_async16(d0 + 3 * TILE_B, Bl0 + t0);
        cp_async16(d1 + 3 * TILE_B, Bl0 + t1);
        cp_commit();
    };

    float acc[2][8][4];
    #pragma unroll
    for (int mt = 0; mt < 2; mt++)
        #pragma unroll
        for (int nt = 0; nt < 8; nt++)
            #pragma unroll
            for (int j = 0; j < 4; j++) acc[mt][nt][j] = 0.f;

    stage(0, 0);
    stage(1, 1);

    // precomputed intra-tile ldsm offsets (buffer base added per kb)
    const uint32_t aoff0 = (uint32_t)((warp_m * 32 + (lane & 15)) * 80 + ((lane >> 4) * 16));
    const int g = lane >> 3;
    const uint32_t boffB = (uint32_t)((warp_n * 64 + (g >> 1) * 8 + (lane & 7)) * 80 + (g & 1) * 16);

    #pragma unroll 1
    for (int kb = 0; kb < NB; kb++) {
        if (kb + 1 < NB) cp_wait_n<1>(); else cp_wait_n<0>();
        __syncthreads();
        uint32_t bufb = sb + (kb & 1) * BUF_B;

        #pragma unroll
        for (int ks = 0; ks < 2; ks++) {
            uint32_t ah[2][4], al[2][4];
            #pragma unroll
            for (int mt = 0; mt < 2; mt++) {
                uint32_t aoff = aoff0 + (uint32_t)(mt * 16 * 80 + ks * 32);
                ldsm4(ah[mt], bufb + aoff);
                ldsm4(al[mt], bufb + TILE_B + aoff);
            }
            #pragma unroll
            for (int pq = 0; pq < 2; pq++) {     // p-pairs: p = 2*pq, 2*pq+1
                uint32_t bh[2][4], bl[2][4];
                #pragma unroll
                for (int pi = 0; pi < 2; pi++) {
                    int p = 2 * pq + pi;
                    uint32_t boff = boffB + (uint32_t)(p * 16 * 80 + ks * 32);
                    ldsm4(bh[pi], bufb + 2 * TILE_B + boff);
                    ldsm4(bl[pi], bufb + 3 * TILE_B + boff);
                }
                // term-major: same accumulator reused only every 8 MMAs
                #pragma unroll
                for (int pi = 0; pi < 2; pi++)
                    #pragma unroll
                    for (int half = 0; half < 2; half++)
                        #pragma unroll
                        for (int mt = 0; mt < 2; mt++)
                            mma16816(acc[mt][4 * pq + 2 * pi + half], ah[mt],
                                     bh[pi][2 * half], bh[pi][2 * half + 1]);
                #pragma unroll
                for (int pi = 0; pi < 2; pi++)
                    #pragma unroll
                    for (int half = 0; half < 2; half++)
                        #pragma unroll
                        for (int mt = 0; mt < 2; mt++)
                            mma16816(acc[mt][4 * pq + 2 * pi + half], ah[mt],
                                     bl[pi][2 * half], bl[pi][2 * half + 1]);
                #pragma unroll
                for (int pi = 0; pi < 2; pi++)
                    #pragma unroll
                    for (int half = 0; half < 2; half++)
                        #pragma unroll
                        for (int mt = 0; mt < 2; mt++)
                            mma16816(acc[mt][4 * pq + 2 * pi + half], al[mt],
                                     bh[pi][2 * half], bh[pi][2 * half + 1]);
            }
        }
        __syncthreads();
        if (kb + 2 < NB) stage(kb & 1, kb + 2);
    }

    // ---- epilogue ----
    const int gq = lane >> 2, tq = lane & 3;
    #pragma unroll
    for (int mt = 0; mt < 2; mt++) {
        int rA = m0 + warp_m * 32 + mt * 16 + gq;
        int rB = rA + 8;
        #pragma unroll
        for (int nt = 0; nt < 8; nt++) {
            int col = n0 + warp_n * 64 + nt * 8 + tq * 2;
            if (IS1) {
                float2 bv = *(const float2*)&bp[col];
                float y0 = fmaxf(acc[mt][nt][0] + bv.x, 0.f);
                float y1 = fmaxf(acc[mt][nt][1] + bv.y, 0.f);
                float y2 = fmaxf(acc[mt][nt][2] + bv.x, 0.f);
                float y3 = fmaxf(acc[mt][nt][3] + bv.y, 0.f);
                __nv_bfloat16 h0, l0, h1, l1, h2, l2, h3, l3;
                split_bf16(y0, h0, l0); split_bf16(y1, h1, l1);
                split_bf16(y2, h2, l2); split_bf16(y3, h3, l3);
                __nv_bfloat162 pha; pha.x = h0; pha.y = h1;
                __nv_bfloat162 pla; pla.x = l0; pla.y = l1;
                __nv_bfloat162 phb; phb.x = h2; phb.y = h3;
                __nv_bfloat162 plb; plb.x = l2; plb.y = l3;
                *(__nv_bfloat162*)(g_Hh + (size_t)rA * DFF_ + col) = pha;
                *(__nv_bfloat162*)(g_Hl + (size_t)rA * DFF_ + col) = pla;
                *(__nv_bfloat162*)(g_Hh + (size_t)rB * DFF_ + col) = phb;
                *(__nv_bfloat162*)(g_Hl + (size_t)rB * DFF_ + col) = plb;
            } else {
                if (col < L_) {
                    float2 bv = *(const float2*)&bp[col];
                    float2* zpA = (float2*)(g_Z + (size_t)rA * L_ + col);
                    float2* zpB = (float2*)(g_Z + (size_t)rB * L_ + col);
                    float2 zA = *zpA, zB = *zpB;
                    float z0 = zA.x + acc[mt][nt][0] + bv.x;
                    float z1 = zA.y + acc[mt][nt][1] + bv.y;
                    float z2 = zB.x + acc[mt][nt][2] + bv.x;
                    float z3 = zB.y + acc[mt][nt][3] + bv.y;
                    *zpA = make_float2(z0, z1);
                    *zpB = make_float2(z2, z3);
                    __nv_bfloat16 h0, l0, h1, l1, h2, l2, h3, l3;
                    split_bf16(z0, h0, l0); split_bf16(z1, h1, l1);
                    split_bf16(z2, h2, l2); split_bf16(z3, h3, l3);
                    __nv_bfloat162 pha; pha.x = h0; pha.y = h1;
                    __nv_bfloat162 pla; pla.x = l0; pla.y = l1;
                    __nv_bfloat162 phb; phb.x = h2; phb.y = h3;
                    __nv_bfloat162 plb; plb.x = l2; plb.y = l3;
                    *(__nv_bfloat162*)(g_Zh + (size_t)rA * KPAD + col) = pha;
                    *(__nv_bfloat162*)(g_Zl + (size_t)rA * KPAD + col) = pla;
                    *(__nv_bfloat162*)(g_Zh + (size_t)rB * KPAD + col) = phb;
                    *(__nv_bfloat162*)(g_Zl + (size_t)rB * KPAD + col) = plb;
                }
            }
        }
    }
}

// ------------------------- head + denorm + transpose ----------------
__global__ void head_kernel(const float* __restrict__ Wh,
                            const float* __restrict__ bh,
                            const float* __restrict__ rev_w,
                            const float* __restrict__ rev_b,
                            float* __restrict__ out) {
    int prow = blockIdx.x;
    int c = g_chan[prow];
    if (c < 0) return;
    int kc = g_clusprow[prow];

    __shared__ __align__(16) float Zs[32][65];
    __shared__ __align__(16) float Ws[64][96];

    int tid = threadIdx.x;       // 256
    int row = tid & 31;
    int cg  = tid >> 5;
    float acc[12];
    #pragma unroll
    for (int j = 0; j < 12; j++) acc[j] = 0.f;

    const float* Whk = Wh + (size_t)kc * L_ * O_;
    for (int l0 = 0; l0 < L_; l0 += 64) {
        int lc = min(64, L_ - l0);
        for (int i = tid; i < 32 * 64; i += 256) {
            int rr = i >> 6, ll = i & 63;
            Zs[rr][ll] = (ll < lc) ? g_Z[(size_t)(prow * 32 + rr) * L_ + l0 + ll] : 0.f;
        }
        for (int i = tid; i < 64 * 96; i += 256) {
            int ll = i / 96, o = i - ll * 96;
            Ws[ll][o] = (ll < lc) ? Whk[(size_t)(l0 + ll) * O_ + o] : 0.f;
        }
        __syncthreads();
        #pragma unroll 8
        for (int ll = 0; ll < 64; ll++) {
            float a = Zs[row][ll];
            float4 w0 = *(const float4*)&Ws[ll][cg * 12];
            float4 w1 = *(const float4*)&Ws[ll][cg * 12 + 4];
            float4 w2 = *(const float4*)&Ws[ll][cg * 12 + 8];
            acc[0]  += a * w0.x; acc[1]  += a * w0.y; acc[2]  += a * w0.z; acc[3]  += a * w0.w;
            acc[4]  += a * w1.x; acc[5]  += a * w1.y; acc[6]  += a * w1.z; acc[7]  += a * w1.w;
            acc[8]  += a * w2.x; acc[9]  += a * w2.y; acc[10] += a * w2.z; acc[11] += a * w2.w;
        }
        __syncthreads();
    }

    int rg = prow * 32 + row;
    float mean = g_mean[rg], stdv = g_std[rg];
    float w = rev_w[c], rb = rev_b[c];
    float scale = stdv / w;
    #pragma unroll
    for (int j = 0; j < 12; j++) {
        int o = cg * 12 + j;
        float y = acc[j] + bh[kc * O_ + o];
        out[((size_t)row * O_ + o) * C_ + c] = (y - rb) * scale + mean;
    }
}

// ------------------------- launch ----------------------------------
extern "C" void kernel_launch(void* const* d_in, const int* in_sizes, int n_in,
                              void* d_out, int out_size) {
    const float* x     = (const float*)d_in[0];
    const float* rev_w = (const float*)d_in[1];
    const float* rev_b = (const float*)d_in[2];
    const float* W1    = (const float*)d_in[3];
    const float* b1    = (const float*)d_in[4];
    const float* W2    = (const float*)d_in[5];
    const float* b2    = (const float*)d_in[6];
    const float* Wh    = (const float*)d_in[7];
    const float* bh    = (const float*)d_in[8];
    const int*   assign = (const int*)d_in[9];
    float* out = (float*)d_out;

    cudaFuncSetAttribute(ffn_mma<true>,  cudaFuncAttributeMaxDynamicSharedMemorySize, FFN_SMEM);
    cudaFuncSetAttribute(ffn_mma<false>, cudaFuncAttributeMaxDynamicSharedMemorySize, FFN_SMEM);

    prep_kernel<<<1, 256>>>(assign);
    convW1_kernel<<<dim3(DFF_ / 32, KPAD / 32, KC_ * NL_), dim3(32, 8)>>>(W1);
    convW2_kernel<<<dim3(DFF_ / 32, KPAD / 32, KC_ * NL_), dim3(32, 8)>>>(W2);
    revin_kernel<<<MTOT, 128>>>(x, rev_w, rev_b);
    for (int l = 0; l < NL_; l++) {
        ffn_mma<true ><<<dim3(DFF_ / 128, NGRP), 256, FFN_SMEM>>>(b1, l);
        ffn_mma<false><<<dim3(KPAD / 128, NGRP), 256, FFN_SMEM>>>(b2, l);
    }
    head_kernel<<<PROWS, 256>>>(Wh, bh, rev_w, rev_b, out);
}

// round 11
// speedup vs baseline: 2.2157x; 1.1205x over previous
#include <cuda_runtime.h>
#include <cuda_bf16.h>
#include <cstdint>

#define B_    32
#define C_    256
#define L_    336
#define O_    96
#define KC_   4
#define NL_   2
#define DFF_  1024
#define KPAD  384              // L_ padded for k-blocking AND ffn2 n staging
#define PROWS 268
#define NGRP  67
#define MGRP  134              // 64-row m-groups (prow pairs)
#define MTOT  (PROWS * 32)     // 8576 rows (prow*32 + b)

// ------------------------- device scratch -------------------------
__device__ float g_Z[(size_t)MTOT * L_];                 // residual stream fp32
__device__ __nv_bfloat16 g_Zh[(size_t)MTOT * KPAD];      // z split hi
__device__ __nv_bfloat16 g_Zl[(size_t)MTOT * KPAD];      // z split lo
__device__ __nv_bfloat16 g_Hh[(size_t)MTOT * DFF_];      // hidden hi
__device__ __nv_bfloat16 g_Hl[(size_t)MTOT * DFF_];      // hidden lo
__device__ __nv_bfloat16 g_W1T_h[(size_t)KC_ * NL_ * DFF_ * KPAD];  // [kl][n][k]
__device__ __nv_bfloat16 g_W1T_l[(size_t)KC_ * NL_ * DFF_ * KPAD];
__device__ __nv_bfloat16 g_W2T_h[(size_t)KC_ * NL_ * KPAD * DFF_];  // [kl][n(384)][d]
__device__ __nv_bfloat16 g_W2T_l[(size_t)KC_ * NL_ * KPAD * DFF_];
__device__ float g_mean[MTOT];
__device__ float g_std[MTOT];
__device__ int   g_chan[PROWS];
__device__ int   g_clusprow[PROWS];
__device__ int   g_clusgrp[NGRP];

// ------------------------- PTX helpers -----------------------------
__device__ __forceinline__ void ldsm4(uint32_t* r, uint32_t addr) {
    asm volatile("ldmatrix.sync.aligned.m8n8.x4.shared.b16 {%0,%1,%2,%3}, [%4];"
                 : "=r"(r[0]), "=r"(r[1]), "=r"(r[2]), "=r"(r[3]) : "r"(addr));
}
__device__ __forceinline__ void mma16816(float* d, const uint32_t* a,
                                         uint32_t b0, uint32_t b1) {
    asm volatile("mma.sync.aligned.m16n8k16.row.col.f32.bf16.bf16.f32 "
                 "{%0,%1,%2,%3}, {%4,%5,%6,%7}, {%8,%9}, {%0,%1,%2,%3};"
                 : "+f"(d[0]), "+f"(d[1]), "+f"(d[2]), "+f"(d[3])
                 : "r"(a[0]), "r"(a[1]), "r"(a[2]), "r"(a[3]), "r"(b0), "r"(b1));
}
__device__ __forceinline__ void cp_async16(uint32_t dst, const void* src) {
    asm volatile("cp.async.cg.shared.global [%0], [%1], 16;" :: "r"(dst), "l"(src));
}
__device__ __forceinline__ void cp_commit() { asm volatile("cp.async.commit_group;"); }
template <int N> __device__ __forceinline__ void cp_wait_n() {
    asm volatile("cp.async.wait_group %0;" :: "n"(N));
}
__device__ __forceinline__ void split_bf16(float y, __nv_bfloat16& h, __nv_bfloat16& l) {
    h = __float2bfloat16(y);
    l = __float2bfloat16(y - __bfloat162float(h));
}

// ------------------------- prep: bucket channels by cluster --------
__global__ void prep_kernel(const int* __restrict__ assign) {
    __shared__ int sa[C_];
    __shared__ int cnt[KC_];
    __shared__ int base[KC_ + 1];
    int t = threadIdx.x;
    if (t < KC_) cnt[t] = 0;
    __syncthreads();
    if (t < C_) {
        int k = assign[t];
        k = min(max(k, 0), KC_ - 1);
        sa[t] = k;
        atomicAdd(&cnt[k], 1);
    }
    __syncthreads();
    if (t == 0) {
        base[0] = 0;
        for (int k = 0; k < KC_; k++) base[k + 1] = base[k] + ((cnt[k] + 3) & ~3);
    }
    __syncthreads();
    for (int p = t; p < PROWS; p += blockDim.x) {
        int kk = 0;
        for (int k = 0; k < KC_; k++) if (p >= base[k + 1]) kk = k + 1;
        if (kk >= KC_) kk = 0;
        g_clusprow[p] = kk;
        g_chan[p] = -1;
    }
    __syncthreads();   // defaults visible before real channel writes
    if (t < C_) {
        int k = sa[t];
        int rank = 0;
        for (int c = 0; c < t; c++) rank += (sa[c] == k);
        g_chan[base[k] + rank] = t;
    }
    if (t < NGRP) {
        int p = t * 4;
        int kk = 0;
        for (int k = 0; k < KC_; k++) if (p >= base[k + 1]) kk = k + 1;
        if (kk >= KC_) kk = 0;
        g_clusgrp[t] = kk;
    }
}

// ------------------------- weight transpose + bf16 split -----------
// W1 [kl][336][1024] -> W1T_h/l [kl][1024][384]
__global__ void convW1_kernel(const float* __restrict__ W1) {
    __shared__ float tile[32][33];
    int n0 = blockIdx.x * 32, k0 = blockIdx.y * 32, kl = blockIdx.z;
    int tx = threadIdx.x, ty = threadIdx.y;
    const float* src = W1 + (size_t)kl * L_ * DFF_;
    for (int r = ty; r < 32; r += 8) {
        int k = k0 + r;
        tile[r][tx] = (k < L_) ? src[(size_t)k * DFF_ + n0 + tx] : 0.f;
    }
    __syncthreads();
    for (int r = ty; r < 32; r += 8) {
        int n = n0 + r, k = k0 + tx;
        float v = tile[tx][r];
        __nv_bfloat16 h, l; split_bf16(v, h, l);
        size_t o = ((size_t)kl * DFF_ + n) * KPAD + k;
        g_W1T_h[o] = h; g_W1T_l[o] = l;
    }
}

// W2 [kl][1024][336] -> W2T_h/l [kl][384][1024]
__global__ void convW2_kernel(const float* __restrict__ W2) {
    __shared__ float tile[32][33];
    int d0 = blockIdx.x * 32, n0 = blockIdx.y * 32, kl = blockIdx.z;
    int tx = threadIdx.x, ty = threadIdx.y;
    const float* src = W2 + (size_t)kl * DFF_ * L_;
    for (int r = ty; r < 32; r += 8) {
        int n = n0 + tx;
        tile[r][tx] = (n < L_) ? src[(size_t)(d0 + r) * L_ + n] : 0.f;
    }
    __syncthreads();
    for (int r = ty; r < 32; r += 8) {
        int n = n0 + r, d = d0 + tx;
        float v = tile[tx][r];
        __nv_bfloat16 h, l; split_bf16(v, h, l);
        size_t o = ((size_t)kl * KPAD + n) * DFF_ + d;
        g_W2T_h[o] = h; g_W2T_l[o] = l;
    }
}

// ------------------------- RevIN normalize -------------------------
__global__ void revin_kernel(const float* __restrict__ x,
                             const float* __restrict__ rev_w,
                             const float* __restrict__ rev_b) {
    int r = blockIdx.x;
    int prow = r >> 5, b = r & 31;
    int c = g_chan[prow];
    int t = threadIdx.x;            // 128
    __shared__ float sx[L_];
    __shared__ float sred[8];
    float* zr = g_Z + (size_t)r * L_;
    __nv_bfloat16* zh = g_Zh + (size_t)r * KPAD;
    __nv_bfloat16* zl = g_Zl + (size_t)r * KPAD;

    if (c < 0) {
        for (int i = t; i < L_; i += 128) zr[i] = 0.f;
        for (int i = t; i < KPAD; i += 128) { zh[i] = __float2bfloat16(0.f); zl[i] = __float2bfloat16(0.f); }
        if (t == 0) { g_mean[r] = 0.f; g_std[r] = 1.f; }
        return;
    }
    const float* xr = x + ((size_t)b * C_ + c) * L_;
    float s = 0.f;
    for (int i = t; i < L_; i += 128) { float v = xr[i]; sx[i] = v; s += v; }
    #pragma unroll
    for (int o = 16; o > 0; o >>= 1) s += __shfl_down_sync(0xffffffffu, s, o);
    if ((t & 31) == 0) sred[t >> 5] = s;
    __syncthreads();
    if (t < 32) {
        float v = (t < 4) ? sred[t] : 0.f;
        v += __shfl_down_sync(0xffffffffu, v, 2);
        v += __shfl_down_sync(0xffffffffu, v, 1);
        if (t == 0) sred[4] = v;
    }
    __syncthreads();
    float mean = sred[4] * (1.0f / L_);

    float vs = 0.f;
    for (int i = t; i < L_; i += 128) { float d = sx[i] - mean; vs += d * d; }
    #pragma unroll
    for (int o = 16; o > 0; o >>= 1) vs += __shfl_down_sync(0xffffffffu, vs, o);
    if ((t & 31) == 0) sred[t >> 5] = vs;
    __syncthreads();
    if (t < 32) {
        float v = (t < 4) ? sred[t] : 0.f;
        v += __shfl_down_sync(0xffffffffu, v, 2);
        v += __shfl_down_sync(0xffffffffu, v, 1);
        if (t == 0) sred[5] = v;
    }
    __syncthreads();
    float var  = sred[5] * (1.0f / L_);
    float stdv = sqrtf(var + 1e-5f);
    float w  = rev_w[c], rb = rev_b[c];
    float rs = w / stdv;
    for (int i = t; i < L_; i += 128) {
        float v = (sx[i] - mean) * rs + rb;
        zr[i] = v;
        __nv_bfloat16 h, l; split_bf16(v, h, l);
        zh[i] = h; zl[i] = l;
    }
    for (int i = L_ + t; i < KPAD; i += 128) { zh[i] = __float2bfloat16(0.f); zl[i] = __float2bfloat16(0.f); }
    if (t == 0) { g_mean[r] = mean; g_std[r] = stdv; }
}

// ------------------------- HMMA FFN GEMMs --------------------------
// D[64, NT*16] = A[64,K] @ W[K,NT*16] via 3-term bf16 split on mma.sync.
// 128 thr = 4 warps (2m x 2n), warp tile 32 x (NT*8), k-block 32, dbl buffer.
// FFN1: NT=8 (N-tile 128); FFN2: NT=7 (N-tile 112 -> no N padding compute).
// smem rows stride 80B -> conflict-free ldmatrix.
#define A_TILE_B 5120                  // 64*80
#define B_TILE_B 10240                 // 128*80
#define BUF_B    (2 * A_TILE_B + 2 * B_TILE_B)   // 30720
#define FFN_SMEM (2 * BUF_B)                     // 61440

template <bool IS1>
__global__ __launch_bounds__(128, 3) void ffn_mma(const float* __restrict__ bias, int layer) {
    constexpr int NB   = IS1 ? 11 : (DFF_ / 32);   // 11 : 32 k-blocks
    constexpr int NT   = IS1 ? 8 : 7;              // n-frags per warp
    constexpr int WN   = NT * 8;                   // warp n extent (64 / 56)
    constexpr int ASTR = IS1 ? KPAD : DFF_;
    constexpr int BSTR = IS1 ? KPAD : DFF_;

    extern __shared__ char smem[];
    uint32_t sb = (uint32_t)__cvta_generic_to_shared(smem);
    const int tid  = threadIdx.x;
    const int wid  = tid >> 5, lane = tid & 31;
    const int warp_m = wid & 1;        // 0..1 -> m offset 32*warp_m
    const int warp_n = wid >> 1;       // 0..1 -> n offset WN*warp_n

    const int n0 = blockIdx.x * (2 * WN);
    const int m0 = blockIdx.y * 64;
    const int kl = g_clusprow[blockIdx.y * 2] * NL_ + layer;

    const __nv_bfloat16* Ah0 = (IS1 ? g_Zh : g_Hh) + (size_t)m0 * ASTR;
    const __nv_bfloat16* Al0 = (IS1 ? g_Zl : g_Hl) + (size_t)m0 * ASTR;
    const __nv_bfloat16* Bh0 = (IS1 ? g_W1T_h : g_W2T_h) +
                               ((size_t)kl * (IS1 ? DFF_ : KPAD) + n0) * BSTR;
    const __nv_bfloat16* Bl0 = (IS1 ? g_W1T_l : g_W2T_l) +
                               ((size_t)kl * (IS1 ? DFF_ : KPAD) + n0) * BSTR;
    const float* bp = bias + (size_t)kl * (IS1 ? DFF_ : L_);

    // staging: 16B chunks, row stride 80B. A tiles 64 rows, B tiles 128 rows.
    auto stage = [&](int buf, int kb) {
        uint32_t base = sb + buf * BUF_B;
        #pragma unroll
        for (int j = 0; j < 2; j++) {                 // A: 256 chunks per tile
            int idx = tid + j * 128;
            int row = idx >> 2, c = idx & 3;
            uint32_t d = base + (uint32_t)(row * 80 + c * 16);
            size_t s = (size_t)row * ASTR + kb * 32 + c * 8;
            cp_async16(d,            Ah0 + s);
            cp_async16(d + A_TILE_B, Al0 + s);
        }
        #pragma unroll
        for (int j = 0; j < 4; j++) {                 // B: 512 chunks per tile
            int idx = tid + j * 128;
            int row = idx >> 2, c = idx & 3;
            uint32_t d = base + 2 * A_TILE_B + (uint32_t)(row * 80 + c * 16);
            size_t s = (size_t)row * BSTR + kb * 32 + c * 8;
            cp_async16(d,            Bh0 + s);
            cp_async16(d + B_TILE_B, Bl0 + s);
        }
        cp_commit();
    };

    float acc[2][NT][4];
    #pragma unroll
    for (int mt = 0; mt < 2; mt++)
        #pragma unroll
        for (int nt = 0; nt < NT; nt++)
            #pragma unroll
            for (int j = 0; j < 4; j++) acc[mt][nt][j] = 0.f;

    stage(0, 0);
    stage(1, 1);

    const uint32_t aoff0 = (uint32_t)((warp_m * 32 + (lane & 15)) * 80 + ((lane >> 4) * 16));
    const int g = lane >> 3;
    const uint32_t boffB = (uint32_t)((warp_n * WN + (g >> 1) * 8 + (lane & 7)) * 80 + (g & 1) * 16);

    #pragma unroll 1
    for (int kb = 0; kb < NB; kb++) {
        if (kb + 1 < NB) cp_wait_n<1>(); else cp_wait_n<0>();
        __syncthreads();
        uint32_t bufb = sb + (kb & 1) * BUF_B;

        #pragma unroll
        for (int ks = 0; ks < 2; ks++) {
            // FFN1 k-trim: k 336..351 are zero pad; skip the last half-block
            if (IS1 && kb == 10 && ks == 1) continue;
            uint32_t ah[2][4], al[2][4];
            #pragma unroll
            for (int mt = 0; mt < 2; mt++) {
                uint32_t aoff = aoff0 + (uint32_t)(mt * 16 * 80 + ks * 32);
                ldsm4(ah[mt], bufb + aoff);
                ldsm4(al[mt], bufb + A_TILE_B + aoff);
            }
            #pragma unroll
            for (int pq = 0; pq < 4; pq++) {     // n-frag pairs (last may be half)
                uint32_t bh[4], bl[4];
                uint32_t boff = boffB + (uint32_t)(pq * 16 * 80 + ks * 32);
                ldsm4(bh, bufb + 2 * A_TILE_B + boff);
                ldsm4(bl, bufb + 2 * A_TILE_B + B_TILE_B + boff);
                // term-major to spread accumulator RAW reuse
                #pragma unroll
                for (int half = 0; half < 2; half++) {
                    int nt = 2 * pq + half;
                    if (nt < NT) {
                        #pragma unroll
                        for (int mt = 0; mt < 2; mt++)
                            mma16816(acc[mt][nt], ah[mt], bh[2 * half], bh[2 * half + 1]);
                    }
                }
                #pragma unroll
                for (int half = 0; half < 2; half++) {
                    int nt = 2 * pq + half;
                    if (nt < NT) {
                        #pragma unroll
                        for (int mt = 0; mt < 2; mt++)
                            mma16816(acc[mt][nt], ah[mt], bl[2 * half], bl[2 * half + 1]);
                    }
                }
                #pragma unroll
                for (int half = 0; half < 2; half++) {
                    int nt = 2 * pq + half;
                    if (nt < NT) {
                        #pragma unroll
                        for (int mt = 0; mt < 2; mt++)
                            mma16816(acc[mt][nt], al[mt], bh[2 * half], bh[2 * half + 1]);
                    }
                }
            }
        }
        __syncthreads();
        if (kb + 2 < NB) stage(kb & 1, kb + 2);
    }

    // ---- epilogue ----
    const int gq = lane >> 2, tq = lane & 3;
    #pragma unroll
    for (int mt = 0; mt < 2; mt++) {
        int rA = m0 + warp_m * 32 + mt * 16 + gq;
        int rB = rA + 8;
        #pragma unroll
        for (int nt = 0; nt < NT; nt++) {
            int col = n0 + warp_n * WN + nt * 8 + tq * 2;
            if (IS1) {
                float2 bv = *(const float2*)&bp[col];
                float y0 = fmaxf(acc[mt][nt][0] + bv.x, 0.f);
                float y1 = fmaxf(acc[mt][nt][1] + bv.y, 0.f);
                float y2 = fmaxf(acc[mt][nt][2] + bv.x, 0.f);
                float y3 = fmaxf(acc[mt][nt][3] + bv.y, 0.f);
                __nv_bfloat16 h0, l0, h1, l1, h2, l2, h3, l3;
                split_bf16(y0, h0, l0); split_bf16(y1, h1, l1);
                split_bf16(y2, h2, l2); split_bf16(y3, h3, l3);
                __nv_bfloat162 pha; pha.x = h0; pha.y = h1;
                __nv_bfloat162 pla; pla.x = l0; pla.y = l1;
                __nv_bfloat162 phb; phb.x = h2; phb.y = h3;
                __nv_bfloat162 plb; plb.x = l2; plb.y = l3;
                *(__nv_bfloat162*)(g_Hh + (size_t)rA * DFF_ + col) = pha;
                *(__nv_bfloat162*)(g_Hl + (size_t)rA * DFF_ + col) = pla;
                *(__nv_bfloat162*)(g_Hh + (size_t)rB * DFF_ + col) = phb;
                *(__nv_bfloat162*)(g_Hl + (size_t)rB * DFF_ + col) = plb;
            } else {
                // NT=7 tiling: col <= 334 always (3*112 = 336 exact)
                float2 bv = *(const float2*)&bp[col];
                float2* zpA = (float2*)(g_Z + (size_t)rA * L_ + col);
                float2* zpB = (float2*)(g_Z + (size_t)rB * L_ + col);
                float2 zA = *zpA, zB = *zpB;
                float z0 = zA.x + acc[mt][nt][0] + bv.x;
                float z1 = zA.y + acc[mt][nt][1] + bv.y;
                float z2 = zB.x + acc[mt][nt][2] + bv.x;
                float z3 = zB.y + acc[mt][nt][3] + bv.y;
                *zpA = make_float2(z0, z1);
                *zpB = make_float2(z2, z3);
                __nv_bfloat16 h0, l0, h1, l1, h2, l2, h3, l3;
                split_bf16(z0, h0, l0); split_bf16(z1, h1, l1);
                split_bf16(z2, h2, l2); split_bf16(z3, h3, l3);
                __nv_bfloat162 pha; pha.x = h0; pha.y = h1;
                __nv_bfloat162 pla; pla.x = l0; pla.y = l1;
                __nv_bfloat162 phb; phb.x = h2; phb.y = h3;
                __nv_bfloat162 plb; plb.x = l2; plb.y = l3;
                *(__nv_bfloat162*)(g_Zh + (size_t)rA * KPAD + col) = pha;
                *(__nv_bfloat162*)(g_Zl + (size_t)rA * KPAD + col) = pla;
                *(__nv_bfloat162*)(g_Zh + (size_t)rB * KPAD + col) = phb;
                *(__nv_bfloat162*)(g_Zl + (size_t)rB * KPAD + col) = plb;
            }
        }
    }
}

// ------------------------- head + denorm + transpose ----------------
__global__ void head_kernel(const float* __restrict__ Wh,
                            const float* __restrict__ bh,
                            const float* __restrict__ rev_w,
                            const float* __restrict__ rev_b,
                            float* __restrict__ out) {
    int prow = blockIdx.x;
    int c = g_chan[prow];
    if (c < 0) return;
    int kc = g_clusprow[prow];

    __shared__ __align__(16) float Zs[32][65];
    __shared__ __align__(16) float Ws[64][96];

    int tid = threadIdx.x;       // 256
    int row = tid & 31;
    int cg  = tid >> 5;
    float acc[12];
    #pragma unroll
    for (int j = 0; j < 12; j++) acc[j] = 0.f;

    const float* Whk = Wh + (size_t)kc * L_ * O_;
    for (int l0 = 0; l0 < L_; l0 += 64) {
        int lc = min(64, L_ - l0);
        for (int i = tid; i < 32 * 64; i += 256) {
            int rr = i >> 6, ll = i & 63;
            Zs[rr][ll] = (ll < lc) ? g_Z[(size_t)(prow * 32 + rr) * L_ + l0 + ll] : 0.f;
        }
        for (int i = tid; i < 64 * 96; i += 256) {
            int ll = i / 96, o = i - ll * 96;
            Ws[ll][o] = (ll < lc) ? Whk[(size_t)(l0 + ll) * O_ + o] : 0.f;
        }
        __syncthreads();
        #pragma unroll 8
        for (int ll = 0; ll < 64; ll++) {
            float a = Zs[row][ll];
            float4 w0 = *(const float4*)&Ws[ll][cg * 12];
            float4 w1 = *(const float4*)&Ws[ll][cg * 12 + 4];
            float4 w2 = *(const float4*)&Ws[ll][cg * 12 + 8];
            acc[0]  += a * w0.x; acc[1]  += a * w0.y; acc[2]  += a * w0.z; acc[3]  += a * w0.w;
            acc[4]  += a * w1.x; acc[5]  += a * w1.y; acc[6]  += a * w1.z; acc[7]  += a * w1.w;
            acc[8]  += a * w2.x; acc[9]  += a * w2.y; acc[10] += a * w2.z; acc[11] += a * w2.w;
        }
        __syncthreads();
    }

    int rg = prow * 32 + row;
    float mean = g_mean[rg], stdv = g_std[rg];
    float w = rev_w[c], rb = rev_b[c];
    float scale = stdv / w;
    #pragma unroll
    for (int j = 0; j < 12; j++) {
        int o = cg * 12 + j;
        float y = acc[j] + bh[kc * O_ + o];
        out[((size_t)row * O_ + o) * C_ + c] = (y - rb) * scale + mean;
    }
}

// ------------------------- launch ----------------------------------
extern "C" void kernel_launch(void* const* d_in, const int* in_sizes, int n_in,
                              void* d_out, int out_size) {
    const float* x     = (const float*)d_in[0];
    const float* rev_w = (const float*)d_in[1];
    const float* rev_b = (const float*)d_in[2];
    const float* W1    = (const float*)d_in[3];
    const float* b1    = (const float*)d_in[4];
    const float* W2    = (const float*)d_in[5];
    const float* b2    = (const float*)d_in[6];
    const float* Wh    = (const float*)d_in[7];
    const float* bh    = (const float*)d_in[8];
    const int*   assign = (const int*)d_in[9];
    float* out = (float*)d_out;

    cudaFuncSetAttribute(ffn_mma<true>,  cudaFuncAttributeMaxDynamicSharedMemorySize, FFN_SMEM);
    cudaFuncSetAttribute(ffn_mma<false>, cudaFuncAttributeMaxDynamicSharedMemorySize, FFN_SMEM);

    prep_kernel<<<1, 256>>>(assign);
    convW1_kernel<<<dim3(DFF_ / 32, KPAD / 32, KC_ * NL_), dim3(32, 8)>>>(W1);
    convW2_kernel<<<dim3(DFF_ / 32, KPAD / 32, KC_ * NL_), dim3(32, 8)>>>(W2);
    revin_kernel<<<MTOT, 128>>>(x, rev_w, rev_b);
    for (int l = 0; l < NL_; l++) {
        ffn_mma<true ><<<dim3(DFF_ / 128, MGRP), 128, FFN_SMEM>>>(b1, l);   // 8 x 134
        ffn_mma<false><<<dim3(3,          MGRP), 128, FFN_SMEM>>>(b2, l);   // 3 x 134 (N=112 tiles)
    }
    head_kernel<<<PROWS, 256>>>(Wh, bh, rev_w, rev_b, out);
}

// round 12
// speedup vs baseline: 2.8105x; 1.2685x over previous
#include <cuda_runtime.h>
#include <cuda_fp16.h>
#include <cstdint>

#define B_    32
#define C_    256
#define L_    336
#define O_    96
#define KC_   4
#define NL_   2
#define DFF_  1024
#define KPAD  384              // L_ padded for k-blocking AND ffn2 n staging
#define PROWS 268
#define NGRP  67
#define MGRP  134              // 64-row m-groups (prow pairs)
#define MTOT  (PROWS * 32)     // 8576 rows (prow*32 + b)

// ------------------------- device scratch -------------------------
__device__ float  g_Z[(size_t)MTOT * L_];                // residual stream fp32
__device__ __half g_Za[(size_t)MTOT * KPAD];             // z as single fp16 digit
__device__ __half g_Ha[(size_t)MTOT * DFF_];             // hidden as single fp16 digit
__device__ __half g_W1T_h[(size_t)KC_ * NL_ * DFF_ * KPAD];  // [kl][n][k] 2-digit
__device__ __half g_W1T_l[(size_t)KC_ * NL_ * DFF_ * KPAD];
__device__ __half g_W2T_h[(size_t)KC_ * NL_ * KPAD * DFF_];  // [kl][n(384)][d]
__device__ __half g_W2T_l[(size_t)KC_ * NL_ * KPAD * DFF_];
__device__ float g_mean[MTOT];
__device__ float g_std[MTOT];
__device__ int   g_chan[PROWS];
__device__ int   g_clusprow[PROWS];
__device__ int   g_clusgrp[NGRP];

// ------------------------- PTX helpers -----------------------------
__device__ __forceinline__ void ldsm4(uint32_t* r, uint32_t addr) {
    asm volatile("ldmatrix.sync.aligned.m8n8.x4.shared.b16 {%0,%1,%2,%3}, [%4];"
                 : "=r"(r[0]), "=r"(r[1]), "=r"(r[2]), "=r"(r[3]) : "r"(addr));
}
__device__ __forceinline__ void mma16816(float* d, const uint32_t* a,
                                         uint32_t b0, uint32_t b1) {
    asm volatile("mma.sync.aligned.m16n8k16.row.col.f32.f16.f16.f32 "
                 "{%0,%1,%2,%3}, {%4,%5,%6,%7}, {%8,%9}, {%0,%1,%2,%3};"
                 : "+f"(d[0]), "+f"(d[1]), "+f"(d[2]), "+f"(d[3])
                 : "r"(a[0]), "r"(a[1]), "r"(a[2]), "r"(a[3]), "r"(b0), "r"(b1));
}
__device__ __forceinline__ void cp_async16(uint32_t dst, const void* src) {
    asm volatile("cp.async.cg.shared.global [%0], [%1], 16;" :: "r"(dst), "l"(src));
}
__device__ __forceinline__ void cp_commit() { asm volatile("cp.async.commit_group;"); }
template <int N> __device__ __forceinline__ void cp_wait_n() {
    asm volatile("cp.async.wait_group %0;" :: "n"(N));
}
__device__ __forceinline__ void split_h(float y, __half& h, __half& l) {
    h = __float2half_rn(y);
    l = __float2half_rn(y - __half2float(h));
}

// ------------------------- prep: bucket channels by cluster --------
__global__ void prep_kernel(const int* __restrict__ assign) {
    __shared__ int sa[C_];
    __shared__ int cnt[KC_];
    __shared__ int base[KC_ + 1];
    int t = threadIdx.x;
    if (t < KC_) cnt[t] = 0;
    __syncthreads();
    if (t < C_) {
        int k = assign[t];
        k = min(max(k, 0), KC_ - 1);
        sa[t] = k;
        atomicAdd(&cnt[k], 1);
    }
    __syncthreads();
    if (t == 0) {
        base[0] = 0;
        for (int k = 0; k < KC_; k++) base[k + 1] = base[k] + ((cnt[k] + 3) & ~3);
    }
    __syncthreads();
    for (int p = t; p < PROWS; p += blockDim.x) {
        int kk = 0;
        for (int k = 0; k < KC_; k++) if (p >= base[k + 1]) kk = k + 1;
        if (kk >= KC_) kk = 0;
        g_clusprow[p] = kk;
        g_chan[p] = -1;
    }
    __syncthreads();   // defaults visible before real channel writes
    if (t < C_) {
        int k = sa[t];
        int rank = 0;
        for (int c = 0; c < t; c++) rank += (sa[c] == k);
        g_chan[base[k] + rank] = t;
    }
    if (t < NGRP) {
        int p = t * 4;
        int kk = 0;
        for (int k = 0; k < KC_; k++) if (p >= base[k + 1]) kk = k + 1;
        if (kk >= KC_) kk = 0;
        g_clusgrp[t] = kk;
    }
}

// ------------------------- weight transpose + fp16 2-digit split ---
// W1 [kl][336][1024] -> W1T_h/l [kl][1024][384]
__global__ void convW1_kernel(const float* __restrict__ W1) {
    __shared__ float tile[32][33];
    int n0 = blockIdx.x * 32, k0 = blockIdx.y * 32, kl = blockIdx.z;
    int tx = threadIdx.x, ty = threadIdx.y;
    const float* src = W1 + (size_t)kl * L_ * DFF_;
    for (int r = ty; r < 32; r += 8) {
        int k = k0 + r;
        tile[r][tx] = (k < L_) ? src[(size_t)k * DFF_ + n0 + tx] : 0.f;
    }
    __syncthreads();
    for (int r = ty; r < 32; r += 8) {
        int n = n0 + r, k = k0 + tx;
        float v = tile[tx][r];
        __half h, l; split_h(v, h, l);
        size_t o = ((size_t)kl * DFF_ + n) * KPAD + k;
        g_W1T_h[o] = h; g_W1T_l[o] = l;
    }
}

// W2 [kl][1024][336] -> W2T_h/l [kl][384][1024]
__global__ void convW2_kernel(const float* __restrict__ W2) {
    __shared__ float tile[32][33];
    int d0 = blockIdx.x * 32, n0 = blockIdx.y * 32, kl = blockIdx.z;
    int tx = threadIdx.x, ty = threadIdx.y;
    const float* src = W2 + (size_t)kl * DFF_ * L_;
    for (int r = ty; r < 32; r += 8) {
        int n = n0 + tx;
        tile[r][tx] = (n < L_) ? src[(size_t)(d0 + r) * L_ + n] : 0.f;
    }
    __syncthreads();
    for (int r = ty; r < 32; r += 8) {
        int n = n0 + r, d = d0 + tx;
        float v = tile[tx][r];
        __half h, l; split_h(v, h, l);
        size_t o = ((size_t)kl * KPAD + n) * DFF_ + d;
        g_W2T_h[o] = h; g_W2T_l[o] = l;
    }
}

// ------------------------- RevIN normalize -------------------------
__global__ void revin_kernel(const float* __restrict__ x,
                             const float* __restrict__ rev_w,
                             const float* __restrict__ rev_b) {
    int r = blockIdx.x;
    int prow = r >> 5, b = r & 31;
    int c = g_chan[prow];
    int t = threadIdx.x;            // 128
    __shared__ float sx[L_];
    __shared__ float sred[8];
    float* zr = g_Z + (size_t)r * L_;
    __half* za = g_Za + (size_t)r * KPAD;

    if (c < 0) {
        for (int i = t; i < L_; i += 128) zr[i] = 0.f;
        for (int i = t; i < KPAD; i += 128) za[i] = __float2half(0.f);
        if (t == 0) { g_mean[r] = 0.f; g_std[r] = 1.f; }
        return;
    }
    const float* xr = x + ((size_t)b * C_ + c) * L_;
    float s = 0.f;
    for (int i = t; i < L_; i += 128) { float v = xr[i]; sx[i] = v; s += v; }
    #pragma unroll
    for (int o = 16; o > 0; o >>= 1) s += __shfl_down_sync(0xffffffffu, s, o);
    if ((t & 31) == 0) sred[t >> 5] = s;
    __syncthreads();
    if (t < 32) {
        float v = (t < 4) ? sred[t] : 0.f;
        v += __shfl_down_sync(0xffffffffu, v, 2);
        v += __shfl_down_sync(0xffffffffu, v, 1);
        if (t == 0) sred[4] = v;
    }
    __syncthreads();
    float mean = sred[4] * (1.0f / L_);

    float vs = 0.f;
    for (int i = t; i < L_; i += 128) { float d = sx[i] - mean; vs += d * d; }
    #pragma unroll
    for (int o = 16; o > 0; o >>= 1) vs += __shfl_down_sync(0xffffffffu, vs, o);
    if ((t & 31) == 0) sred[t >> 5] = vs;
    __syncthreads();
    if (t < 32) {
        float v = (t < 4) ? sred[t] : 0.f;
        v += __shfl_down_sync(0xffffffffu, v, 2);
        v += __shfl_down_sync(0xffffffffu, v, 1);
        if (t == 0) sred[5] = v;
    }
    __syncthreads();
    float var  = sred[5] * (1.0f / L_);
    float stdv = sqrtf(var + 1e-5f);
    float w  = rev_w[c], rb = rev_b[c];
    float rs = w / stdv;
    for (int i = t; i < L_; i += 128) {
        float v = (sx[i] - mean) * rs + rb;
        zr[i] = v;
        za[i] = __float2half_rn(v);
    }
    for (int i = L_ + t; i < KPAD; i += 128) za[i] = __float2half(0.f);
    if (t == 0) { g_mean[r] = mean; g_std[r] = stdv; }
}

// ------------------------- HMMA FFN GEMMs --------------------------
// D[64, NT*16] = A[64,K] @ W[K,NT*16], asymmetric fp16 split:
//   A single fp16 digit, B two fp16 digits -> 2 MMAs per k=16 chunk.
// 128 thr = 4 warps (2m x 2n), k-block 32, double buffer, 4 CTAs/SM.
// FFN1: NT=8 (N-tile 128); FFN2: NT=7 (N-tile 112 -> zero N padding).
// smem rows stride 80B -> conflict-free ldmatrix.
#define A_TILE_B 5120                   // 64*80
#define B_TILE_B 10240                  // 128*80
#define BUF_B    (A_TILE_B + 2 * B_TILE_B)   // 25600
#define FFN_SMEM (2 * BUF_B)                 // 51200

template <bool IS1>
__global__ __launch_bounds__(128, 4) void ffn_mma(const float* __restrict__ bias, int layer) {
    constexpr int NB   = IS1 ? 11 : (DFF_ / 32);   // 11 : 32 k-blocks
    constexpr int NT   = IS1 ? 8 : 7;              // n-frags per warp
    constexpr int WN   = NT * 8;                   // warp n extent (64 / 56)
    constexpr int ASTR = IS1 ? KPAD : DFF_;
    constexpr int BSTR = IS1 ? KPAD : DFF_;

    extern __shared__ char smem[];
    uint32_t sb = (uint32_t)__cvta_generic_to_shared(smem);
    const int tid  = threadIdx.x;
    const int wid  = tid >> 5, lane = tid & 31;
    const int warp_m = wid & 1;        // 0..1 -> m offset 32*warp_m
    const int warp_n = wid >> 1;       // 0..1 -> n offset WN*warp_n

    const int n0 = blockIdx.x * (2 * WN);
    const int m0 = blockIdx.y * 64;
    const int kl = g_clusprow[blockIdx.y * 2] * NL_ + layer;

    const __half* Aa0 = (IS1 ? g_Za : g_Ha) + (size_t)m0 * ASTR;
    const __half* Bh0 = (IS1 ? g_W1T_h : g_W2T_h) +
                        ((size_t)kl * (IS1 ? DFF_ : KPAD) + n0) * BSTR;
    const __half* Bl0 = (IS1 ? g_W1T_l : g_W2T_l) +
                        ((size_t)kl * (IS1 ? DFF_ : KPAD) + n0) * BSTR;
    const float* bp = bias + (size_t)kl * (IS1 ? DFF_ : L_);

    // staging: 16B chunks, row stride 80B. A tile 64 rows, B tiles 128 rows.
    auto stage = [&](int buf, int kb) {
        uint32_t base = sb + buf * BUF_B;
        #pragma unroll
        for (int j = 0; j < 2; j++) {                 // A: 256 chunks
            int idx = tid + j * 128;
            int row = idx >> 2, c = idx & 3;
            uint32_t d = base + (uint32_t)(row * 80 + c * 16);
            size_t s = (size_t)row * ASTR + kb * 32 + c * 8;
            cp_async16(d, Aa0 + s);
        }
        #pragma unroll
        for (int j = 0; j < 4; j++) {                 // B: 512 chunks x 2 digits
            int idx = tid + j * 128;
            int row = idx >> 2, c = idx & 3;
            uint32_t d = base + A_TILE_B + (uint32_t)(row * 80 + c * 16);
            size_t s = (size_t)row * BSTR + kb * 32 + c * 8;
            cp_async16(d,            Bh0 + s);
            cp_async16(d + B_TILE_B, Bl0 + s);
        }
        cp_commit();
    };

    float acc[2][NT][4];
    #pragma unroll
    for (int mt = 0; mt < 2; mt++)
        #pragma unroll
        for (int nt = 0; nt < NT; nt++)
            #pragma unroll
            for (int j = 0; j < 4; j++) acc[mt][nt][j] = 0.f;

    stage(0, 0);
    stage(1, 1);

    const uint32_t aoff0 = (uint32_t)((warp_m * 32 + (lane & 15)) * 80 + ((lane >> 4) * 16));
    const int g = lane >> 3;
    const uint32_t boffB = (uint32_t)((warp_n * WN + (g >> 1) * 8 + (lane & 7)) * 80 + (g & 1) * 16);

    #pragma unroll 1
    for (int kb = 0; kb < NB; kb++) {
        if (kb + 1 < NB) cp_wait_n<1>(); else cp_wait_n<0>();
        __syncthreads();
        uint32_t bufb = sb + (kb & 1) * BUF_B;

        #pragma unroll
        for (int ks = 0; ks < 2; ks++) {
            // FFN1 k-trim: k 336..351 are zero pad; skip the last half-block
            if (IS1 && kb == 10 && ks == 1) continue;
            uint32_t ah[2][4];
            #pragma unroll
            for (int mt = 0; mt < 2; mt++) {
                uint32_t aoff = aoff0 + (uint32_t)(mt * 16 * 80 + ks * 32);
                ldsm4(ah[mt], bufb + aoff);
            }
            #pragma unroll
            for (int pq = 0; pq < 4; pq++) {     // n-frag pairs (last may be half)
                uint32_t bh[4], bl[4];
                uint32_t boff = boffB + (uint32_t)(pq * 16 * 80 + ks * 32);
                ldsm4(bh, bufb + A_TILE_B + boff);
                ldsm4(bl, bufb + A_TILE_B + B_TILE_B + boff);
                // term-major: hi digit then lo digit (spreads acc RAW reuse)
                #pragma unroll
                for (int half = 0; half < 2; half++) {
                    int nt = 2 * pq + half;
                    if (nt < NT) {
                        #pragma unroll
                        for (int mt = 0; mt < 2; mt++)
                            mma16816(acc[mt][nt], ah[mt], bh[2 * half], bh[2 * half + 1]);
                    }
                }
                #pragma unroll
                for (int half = 0; half < 2; half++) {
                    int nt = 2 * pq + half;
                    if (nt < NT) {
                        #pragma unroll
                        for (int mt = 0; mt < 2; mt++)
                            mma16816(acc[mt][nt], ah[mt], bl[2 * half], bl[2 * half + 1]);
                    }
                }
            }
        }
        __syncthreads();
        if (kb + 2 < NB) stage(kb & 1, kb + 2);
    }

    // ---- epilogue ----
    const int gq = lane >> 2, tq = lane & 3;
    #pragma unroll
    for (int mt = 0; mt < 2; mt++) {
        int rA = m0 + warp_m * 32 + mt * 16 + gq;
        int rB = rA + 8;
        #pragma unroll
        for (int nt = 0; nt < NT; nt++) {
            int col = n0 + warp_n * WN + nt * 8 + tq * 2;
            if (IS1) {
                float2 bv = *(const float2*)&bp[col];
                float y0 = fmaxf(acc[mt][nt][0] + bv.x, 0.f);
                float y1 = fmaxf(acc[mt][nt][1] + bv.y, 0.f);
                float y2 = fmaxf(acc[mt][nt][2] + bv.x, 0.f);
                float y3 = fmaxf(acc[mt][nt][3] + bv.y, 0.f);
                __half2 pa; pa.x = __float2half_rn(y0); pa.y = __float2half_rn(y1);
                __half2 pb; pb.x = __float2half_rn(y2); pb.y = __float2half_rn(y3);
                *(__half2*)(g_Ha + (size_t)rA * DFF_ + col) = pa;
                *(__half2*)(g_Ha + (size_t)rB * DFF_ + col) = pb;
            } else {
                // NT=7 tiling: col <= 334 always (3*112 = 336 exact)
                float2 bv = *(const float2*)&bp[col];
                float2* zpA = (float2*)(g_Z + (size_t)rA * L_ + col);
                float2* zpB = (float2*)(g_Z + (size_t)rB * L_ + col);
                float2 zA = *zpA, zB = *zpB;
                float z0 = zA.x + acc[mt][nt][0] + bv.x;
                float z1 = zA.y + acc[mt][nt][1] + bv.y;
                float z2 = zB.x + acc[mt][nt][2] + bv.x;
                float z3 = zB.y + acc[mt][nt][3] + bv.y;
                *zpA = make_float2(z0, z1);
                *zpB = make_float2(z2, z3);
                __half2 pa; pa.x = __float2half_rn(z0); pa.y = __float2half_rn(z1);
                __half2 pb; pb.x = __float2half_rn(z2); pb.y = __float2half_rn(z3);
                *(__half2*)(g_Za + (size_t)rA * KPAD + col) = pa;
                *(__half2*)(g_Za + (size_t)rB * KPAD + col) = pb;
            }
        }
    }
}

// ------------------------- head + denorm + transpose ----------------
__global__ void head_kernel(const float* __restrict__ Wh,
                            const float* __restrict__ bh,
                            const float* __restrict__ rev_w,
                            const float* __restrict__ rev_b,
                            float* __restrict__ out) {
    int prow = blockIdx.x;
    int c = g_chan[prow];
    if (c < 0) return;
    int kc = g_clusprow[prow];

    __shared__ __align__(16) float Zs[32][65];
    __shared__ __align__(16) float Ws[64][96];

    int tid = threadIdx.x;       // 256
    int row = tid & 31;
    int cg  = tid >> 5;
    float acc[12];
    #pragma unroll
    for (int j = 0; j < 12; j++) acc[j] = 0.f;

    const float* Whk = Wh + (size_t)kc * L_ * O_;
    for (int l0 = 0; l0 < L_; l0 += 64) {
        int lc = min(64, L_ - l0);
        for (int i = tid; i < 32 * 64; i += 256) {
            int rr = i >> 6, ll = i & 63;
            Zs[rr][ll] = (ll < lc) ? g_Z[(size_t)(prow * 32 + rr) * L_ + l0 + ll] : 0.f;
        }
        for (int i = tid; i < 64 * 96; i += 256) {
            int ll = i / 96, o = i - ll * 96;
            Ws[ll][o] = (ll < lc) ? Whk[(size_t)(l0 + ll) * O_ + o] : 0.f;
        }
        __syncthreads();
        #pragma unroll 8
        for (int ll = 0; ll < 64; ll++) {
            float a = Zs[row][ll];
            float4 w0 = *(const float4*)&Ws[ll][cg * 12];
            float4 w1 = *(const float4*)&Ws[ll][cg * 12 + 4];
            float4 w2 = *(const float4*)&Ws[ll][cg * 12 + 8];
            acc[0]  += a * w0.x; acc[1]  += a * w0.y; acc[2]  += a * w0.z; acc[3]  += a * w0.w;
            acc[4]  += a * w1.x; acc[5]  += a * w1.y; acc[6]  += a * w1.z; acc[7]  += a * w1.w;
            acc[8]  += a * w2.x; acc[9]  += a * w2.y; acc[10] += a * w2.z; acc[11] += a * w2.w;
        }
        __syncthreads();
    }

    int rg = prow * 32 + row;
    float mean = g_mean[rg], stdv = g_std[rg];
    float w = rev_w[c], rb = rev_b[c];
    float scale = stdv / w;
    #pragma unroll
    for (int j = 0; j < 12; j++) {
        int o = cg * 12 + j;
        float y = acc[j] + bh[kc * O_ + o];
        out[((size_t)row * O_ + o) * C_ + c] = (y - rb) * scale + mean;
    }
}

// ------------------------- launch ----------------------------------
extern "C" void kernel_launch(void* const* d_in, const int* in_sizes, int n_in,
                              void* d_out, int out_size) {
    const float* x     = (const float*)d_in[0];
    const float* rev_w = (const float*)d_in[1];
    const float* rev_b = (const float*)d_in[2];
    const float* W1    = (const float*)d_in[3];
    const float* b1    = (const float*)d_in[4];
    const float* W2    = (const float*)d_in[5];
    const float* b2    = (const float*)d_in[6];
    const float* Wh    = (const float*)d_in[7];
    const float* bh    = (const float*)d_in[8];
    const int*   assign = (const int*)d_in[9];
    float* out = (float*)d_out;

    cudaFuncSetAttribute(ffn_mma<true>,  cudaFuncAttributeMaxDynamicSharedMemorySize, FFN_SMEM);
    cudaFuncSetAttribute(ffn_mma<false>, cudaFuncAttributeMaxDynamicSharedMemorySize, FFN_SMEM);

    prep_kernel<<<1, 256>>>(assign);
    convW1_kernel<<<dim3(DFF_ / 32, KPAD / 32, KC_ * NL_), dim3(32, 8)>>>(W1);
    convW2_kernel<<<dim3(DFF_ / 32, KPAD / 32, KC_ * NL_), dim3(32, 8)>>>(W2);
    revin_kernel<<<MTOT, 128>>>(x, rev_w, rev_b);
    for (int l = 0; l < NL_; l++) {
        ffn_mma<true ><<<dim3(DFF_ / 128, MGRP), 128, FFN_SMEM>>>(b1, l);   // 8 x 134
        ffn_mma<false><<<dim3(3,          MGRP), 128, FFN_SMEM>>>(b2, l);   // 3 x 134 (N=112 tiles)
    }
    head_kernel<<<PROWS, 256>>>(Wh, bh, rev_w, rev_b, out);
}

// round 13
// speedup vs baseline: 3.8205x; 1.3594x over previous
#include <cuda_runtime.h>
#include <cuda_fp16.h>
#include <cstdint>

#define B_    32
#define C_    256
#define L_    336
#define O_    96
#define KC_   4
#define NL_   2
#define DFF_  1024
#define KPAD  384              // L_ padded for k-blocking AND ffn2 n staging
#define PROWS 268
#define NGRP  67
#define MGRP  134              // 64-row m-groups (prow pairs)
#define MTOT  (PROWS * 32)     // 8576 rows (prow*32 + b)

// ------------------------- device scratch -------------------------
__device__ float  g_Z[(size_t)MTOT * L_];                // residual stream fp32
__device__ __half g_Za[(size_t)MTOT * KPAD];             // z as single fp16 digit
__device__ __half g_Ha[(size_t)MTOT * DFF_];             // hidden as single fp16 digit
__device__ __half g_W1T[(size_t)KC_ * NL_ * DFF_ * KPAD];  // [kl][n][k] 1 digit
__device__ __half g_W2T[(size_t)KC_ * NL_ * KPAD * DFF_];  // [kl][n(384)][d]
__device__ float g_mean[MTOT];
__device__ float g_std[MTOT];
__device__ int   g_chan[PROWS];
__device__ int   g_clusprow[PROWS];
__device__ int   g_clusgrp[NGRP];

// ------------------------- PTX helpers -----------------------------
__device__ __forceinline__ void ldsm4(uint32_t* r, uint32_t addr) {
    asm volatile("ldmatrix.sync.aligned.m8n8.x4.shared.b16 {%0,%1,%2,%3}, [%4];"
                 : "=r"(r[0]), "=r"(r[1]), "=r"(r[2]), "=r"(r[3]) : "r"(addr));
}
__device__ __forceinline__ void mma16816(float* d, const uint32_t* a,
                                         uint32_t b0, uint32_t b1) {
    asm volatile("mma.sync.aligned.m16n8k16.row.col.f32.f16.f16.f32 "
                 "{%0,%1,%2,%3}, {%4,%5,%6,%7}, {%8,%9}, {%0,%1,%2,%3};"
                 : "+f"(d[0]), "+f"(d[1]), "+f"(d[2]), "+f"(d[3])
                 : "r"(a[0]), "r"(a[1]), "r"(a[2]), "r"(a[3]), "r"(b0), "r"(b1));
}
__device__ __forceinline__ void cp_async16(uint32_t dst, const void* src) {
    asm volatile("cp.async.cg.shared.global [%0], [%1], 16;" :: "r"(dst), "l"(src));
}
__device__ __forceinline__ void cp_commit() { asm volatile("cp.async.commit_group;"); }
template <int N> __device__ __forceinline__ void cp_wait_n() {
    asm volatile("cp.async.wait_group %0;" :: "n"(N));
}

// ------------------------- prep: bucket channels by cluster --------
__global__ void prep_kernel(const int* __restrict__ assign) {
    __shared__ int sa[C_];
    __shared__ int cnt[KC_];
    __shared__ int base[KC_ + 1];
    int t = threadIdx.x;
    if (t < KC_) cnt[t] = 0;
    __syncthreads();
    if (t < C_) {
        int k = assign[t];
        k = min(max(k, 0), KC_ - 1);
        sa[t] = k;
        atomicAdd(&cnt[k], 1);
    }
    __syncthreads();
    if (t == 0) {
        base[0] = 0;
        for (int k = 0; k < KC_; k++) base[k + 1] = base[k] + ((cnt[k] + 3) & ~3);
    }
    __syncthreads();
    for (int p = t; p < PROWS; p += blockDim.x) {
        int kk = 0;
        for (int k = 0; k < KC_; k++) if (p >= base[k + 1]) kk = k + 1;
        if (kk >= KC_) kk = 0;
        g_clusprow[p] = kk;
        g_chan[p] = -1;
    }
    __syncthreads();   // defaults visible before real channel writes
    if (t < C_) {
        int k = sa[t];
        int rank = 0;
        for (int c = 0; c < t; c++) rank += (sa[c] == k);
        g_chan[base[k] + rank] = t;
    }
    if (t < NGRP) {
        int p = t * 4;
        int kk = 0;
        for (int k = 0; k < KC_; k++) if (p >= base[k + 1]) kk = k + 1;
        if (kk >= KC_) kk = 0;
        g_clusgrp[t] = kk;
    }
}

// ------------------------- weight transpose + fp16 convert ---------
// W1 [kl][336][1024] -> W1T [kl][1024][384]
__global__ void convW1_kernel(const float* __restrict__ W1) {
    __shared__ float tile[32][33];
    int n0 = blockIdx.x * 32, k0 = blockIdx.y * 32, kl = blockIdx.z;
    int tx = threadIdx.x, ty = threadIdx.y;
    const float* src = W1 + (size_t)kl * L_ * DFF_;
    for (int r = ty; r < 32; r += 8) {
        int k = k0 + r;
        tile[r][tx] = (k < L_) ? src[(size_t)k * DFF_ + n0 + tx] : 0.f;
    }
    __syncthreads();
    for (int r = ty; r < 32; r += 8) {
        int n = n0 + r, k = k0 + tx;
        g_W1T[((size_t)kl * DFF_ + n) * KPAD + k] = __float2half_rn(tile[tx][r]);
    }
}

// W2 [kl][1024][336] -> W2T [kl][384][1024]
__global__ void convW2_kernel(const float* __restrict__ W2) {
    __shared__ float tile[32][33];
    int d0 = blockIdx.x * 32, n0 = blockIdx.y * 32, kl = blockIdx.z;
    int tx = threadIdx.x, ty = threadIdx.y;
    const float* src = W2 + (size_t)kl * DFF_ * L_;
    for (int r = ty; r < 32; r += 8) {
        int n = n0 + tx;
        tile[r][tx] = (n < L_) ? src[(size_t)(d0 + r) * L_ + n] : 0.f;
    }
    __syncthreads();
    for (int r = ty; r < 32; r += 8) {
        int n = n0 + r, d = d0 + tx;
        g_W2T[((size_t)kl * KPAD + n) * DFF_ + d] = __float2half_rn(tile[tx][r]);
    }
}

// ------------------------- RevIN normalize -------------------------
__global__ void revin_kernel(const float* __restrict__ x,
                             const float* __restrict__ rev_w,
                             const float* __restrict__ rev_b) {
    int r = blockIdx.x;
    int prow = r >> 5, b = r & 31;
    int c = g_chan[prow];
    int t = threadIdx.x;            // 128
    __shared__ float sx[L_];
    __shared__ float sred[8];
    float* zr = g_Z + (size_t)r * L_;
    __half* za = g_Za + (size_t)r * KPAD;

    if (c < 0) {
        for (int i = t; i < L_; i += 128) zr[i] = 0.f;
        for (int i = t; i < KPAD; i += 128) za[i] = __float2half(0.f);
        if (t == 0) { g_mean[r] = 0.f; g_std[r] = 1.f; }
        return;
    }
    const float* xr = x + ((size_t)b * C_ + c) * L_;
    float s = 0.f;
    for (int i = t; i < L_; i += 128) { float v = xr[i]; sx[i] = v; s += v; }
    #pragma unroll
    for (int o = 16; o > 0; o >>= 1) s += __shfl_down_sync(0xffffffffu, s, o);
    if ((t & 31) == 0) sred[t >> 5] = s;
    __syncthreads();
    if (t < 32) {
        float v = (t < 4) ? sred[t] : 0.f;
        v += __shfl_down_sync(0xffffffffu, v, 2);
        v += __shfl_down_sync(0xffffffffu, v, 1);
        if (t == 0) sred[4] = v;
    }
    __syncthreads();
    float mean = sred[4] * (1.0f / L_);

    float vs = 0.f;
    for (int i = t; i < L_; i += 128) { float d = sx[i] - mean; vs += d * d; }
    #pragma unroll
    for (int o = 16; o > 0; o >>= 1) vs += __shfl_down_sync(0xffffffffu, vs, o);
    if ((t & 31) == 0) sred[t >> 5] = vs;
    __syncthreads();
    if (t < 32) {
        float v = (t < 4) ? sred[t] : 0.f;
        v += __shfl_down_sync(0xffffffffu, v, 2);
        v += __shfl_down_sync(0xffffffffu, v, 1);
        if (t == 0) sred[5] = v;
    }
    __syncthreads();
    float var  = sred[5] * (1.0f / L_);
    float stdv = sqrtf(var + 1e-5f);
    float w  = rev_w[c], rb = rev_b[c];
    float rs = w / stdv;
    for (int i = t; i < L_; i += 128) {
        float v = (sx[i] - mean) * rs + rb;
        zr[i] = v;
        za[i] = __float2half_rn(v);
    }
    for (int i = L_ + t; i < KPAD; i += 128) za[i] = __float2half(0.f);
    if (t == 0) { g_mean[r] = mean; g_std[r] = stdv; }
}

// ------------------------- HMMA FFN GEMMs --------------------------
// D[64, NT*16] = A[64,K] @ W[K,NT*16], single fp16 digit both sides:
//   1 MMA per k=16 chunk (error budget: ~3.4e-4 vs 1e-3 threshold).
// 128 thr = 4 warps (2m x 2n), k-block 32, double buffer, 4 CTAs/SM.
// FFN1: NT=8 (N-tile 128); FFN2: NT=7 (N-tile 112 -> zero N padding).
// smem rows stride 80B -> conflict-free ldmatrix.
#define A_TILE_B 5120                   // 64*80
#define B_TILE_B 10240                  // 128*80
#define BUF_B    (A_TILE_B + B_TILE_B)  // 15360
#define FFN_SMEM (2 * BUF_B)            // 30720

template <bool IS1>
__global__ __launch_bounds__(128, 4) void ffn_mma(const float* __restrict__ bias, int layer) {
    constexpr int NB   = IS1 ? 11 : (DFF_ / 32);   // 11 : 32 k-blocks
    constexpr int NT   = IS1 ? 8 : 7;              // n-frags per warp
    constexpr int WN   = NT * 8;                   // warp n extent (64 / 56)
    constexpr int ASTR = IS1 ? KPAD : DFF_;
    constexpr int BSTR = IS1 ? KPAD : DFF_;

    extern __shared__ char smem[];
    uint32_t sb = (uint32_t)__cvta_generic_to_shared(smem);
    const int tid  = threadIdx.x;
    const int wid  = tid >> 5, lane = tid & 31;
    const int warp_m = wid & 1;        // 0..1 -> m offset 32*warp_m
    const int warp_n = wid >> 1;       // 0..1 -> n offset WN*warp_n

    const int n0 = blockIdx.x * (2 * WN);
    const int m0 = blockIdx.y * 64;
    const int kl = g_clusprow[blockIdx.y * 2] * NL_ + layer;

    const __half* Aa0 = (IS1 ? g_Za : g_Ha) + (size_t)m0 * ASTR;
    const __half* Ba0 = (IS1 ? g_W1T : g_W2T) +
                        ((size_t)kl * (IS1 ? DFF_ : KPAD) + n0) * BSTR;
    const float* bp = bias + (size_t)kl * (IS1 ? DFF_ : L_);

    // staging: 16B chunks, row stride 80B. A tile 64 rows, B tile 128 rows.
    auto stage = [&](int buf, int kb) {
        uint32_t base = sb + buf * BUF_B;
        #pragma unroll
        for (int j = 0; j < 2; j++) {                 // A: 256 chunks
            int idx = tid + j * 128;
            int row = idx >> 2, c = idx & 3;
            uint32_t d = base + (uint32_t)(row * 80 + c * 16);
            size_t s = (size_t)row * ASTR + kb * 32 + c * 8;
            cp_async16(d, Aa0 + s);
        }
        #pragma unroll
        for (int j = 0; j < 4; j++) {                 // B: 512 chunks
            int idx = tid + j * 128;
            int row = idx >> 2, c = idx & 3;
            uint32_t d = base + A_TILE_B + (uint32_t)(row * 80 + c * 16);
            size_t s = (size_t)row * BSTR + kb * 32 + c * 8;
            cp_async16(d, Ba0 + s);
        }
        cp_commit();
    };

    float acc[2][NT][4];
    #pragma unroll
    for (int mt = 0; mt < 2; mt++)
        #pragma unroll
        for (int nt = 0; nt < NT; nt++)
            #pragma unroll
            for (int j = 0; j < 4; j++) acc[mt][nt][j] = 0.f;

    stage(0, 0);
    stage(1, 1);

    const uint32_t aoff0 = (uint32_t)((warp_m * 32 + (lane & 15)) * 80 + ((lane >> 4) * 16));
    const int g = lane >> 3;
    const uint32_t boffB = (uint32_t)((warp_n * WN + (g >> 1) * 8 + (lane & 7)) * 80 + (g & 1) * 16);

    #pragma unroll 1
    for (int kb = 0; kb < NB; kb++) {
        if (kb + 1 < NB) cp_wait_n<1>(); else cp_wait_n<0>();
        __syncthreads();
        uint32_t bufb = sb + (kb & 1) * BUF_B;

        #pragma unroll
        for (int ks = 0; ks < 2; ks++) {
            // FFN1 k-trim: k 336..351 are zero pad; skip the last half-block
            if (IS1 && kb == 10 && ks == 1) continue;
            uint32_t ah[2][4];
            #pragma unroll
            for (int mt = 0; mt < 2; mt++) {
                uint32_t aoff = aoff0 + (uint32_t)(mt * 16 * 80 + ks * 32);
                ldsm4(ah[mt], bufb + aoff);
            }
            #pragma unroll
            for (int pq = 0; pq < 4; pq++) {     // n-frag pairs (last may be half)
                uint32_t bh[4];
                uint32_t boff = boffB + (uint32_t)(pq * 16 * 80 + ks * 32);
                ldsm4(bh, bufb + A_TILE_B + boff);
                #pragma unroll
                for (int half = 0; half < 2; half++) {
                    int nt = 2 * pq + half;
                    if (nt < NT) {
                        #pragma unroll
                        for (int mt = 0; mt < 2; mt++)
                            mma16816(acc[mt][nt], ah[mt], bh[2 * half], bh[2 * half + 1]);
                    }
                }
            }
        }
        __syncthreads();
        if (kb + 2 < NB) stage(kb & 1, kb + 2);
    }

    // ---- epilogue ----
    const int gq = lane >> 2, tq = lane & 3;
    #pragma unroll
    for (int mt = 0; mt < 2; mt++) {
        int rA = m0 + warp_m * 32 + mt * 16 + gq;
        int rB = rA + 8;
        #pragma unroll
        for (int nt = 0; nt < NT; nt++) {
            int col = n0 + warp_n * WN + nt * 8 + tq * 2;
            if (IS1) {
                float2 bv = *(const float2*)&bp[col];
                float y0 = fmaxf(acc[mt][nt][0] + bv.x, 0.f);
                float y1 = fmaxf(acc[mt][nt][1] + bv.y, 0.f);
                float y2 = fmaxf(acc[mt][nt][2] + bv.x, 0.f);
                float y3 = fmaxf(acc[mt][nt][3] + bv.y, 0.f);
                __half2 pa; pa.x = __float2half_rn(y0); pa.y = __float2half_rn(y1);
                __half2 pb; pb.x = __float2half_rn(y2); pb.y = __float2half_rn(y3);
                *(__half2*)(g_Ha + (size_t)rA * DFF_ + col) = pa;
                *(__half2*)(g_Ha + (size_t)rB * DFF_ + col) = pb;
            } else {
                // NT=7 tiling: col <= 334 always (3*112 = 336 exact)
                float2 bv = *(const float2*)&bp[col];
                float2* zpA = (float2*)(g_Z + (size_t)rA * L_ + col);
                float2* zpB = (float2*)(g_Z + (size_t)rB * L_ + col);
                float2 zA = *zpA, zB = *zpB;
                float z0 = zA.x + acc[mt][nt][0] + bv.x;
                float z1 = zA.y + acc[mt][nt][1] + bv.y;
                float z2 = zB.x + acc[mt][nt][2] + bv.x;
                float z3 = zB.y + acc[mt][nt][3] + bv.y;
                *zpA = make_float2(z0, z1);
                *zpB = make_float2(z2, z3);
                __half2 pa; pa.x = __float2half_rn(z0); pa.y = __float2half_rn(z1);
                __half2 pb; pb.x = __float2half_rn(z2); pb.y = __float2half_rn(z3);
                *(__half2*)(g_Za + (size_t)rA * KPAD + col) = pa;
                *(__half2*)(g_Za + (size_t)rB * KPAD + col) = pb;
            }
        }
    }
}

// ------------------------- head + denorm + transpose ----------------
__global__ void head_kernel(const float* __restrict__ Wh,
                            const float* __restrict__ bh,
                            const float* __restrict__ rev_w,
                            const float* __restrict__ rev_b,
                            float* __restrict__ out) {
    int prow = blockIdx.x;
    int c = g_chan[prow];
    if (c < 0) return;
    int kc = g_clusprow[prow];

    __shared__ __align__(16) float Zs[32][65];
    __shared__ __align__(16) float Ws[64][96];

    int tid = threadIdx.x;       // 256
    int row = tid & 31;
    int cg  = tid >> 5;
    float acc[12];
    #pragma unroll
    for (int j = 0; j < 12; j++) acc[j] = 0.f;

    const float* Whk = Wh + (size_t)kc * L_ * O_;
    for (int l0 = 0; l0 < L_; l0 += 64) {
        int lc = min(64, L_ - l0);
        for (int i = tid; i < 32 * 64; i += 256) {
            int rr = i >> 6, ll = i & 63;
            Zs[rr][ll] = (ll < lc) ? g_Z[(size_t)(prow * 32 + rr) * L_ + l0 + ll] : 0.f;
        }
        for (int i = tid; i < 64 * 96; i += 256) {
            int ll = i / 96, o = i - ll * 96;
            Ws[ll][o] = (ll < lc) ? Whk[(size_t)(l0 + ll) * O_ + o] : 0.f;
        }
        __syncthreads();
        #pragma unroll 8
        for (int ll = 0; ll < 64; ll++) {
            float a = Zs[row][ll];
            float4 w0 = *(const float4*)&Ws[ll][cg * 12];
            float4 w1 = *(const float4*)&Ws[ll][cg * 12 + 4];
            float4 w2 = *(const float4*)&Ws[ll][cg * 12 + 8];
            acc[0]  += a * w0.x; acc[1]  += a * w0.y; acc[2]  += a * w0.z; acc[3]  += a * w0.w;
            acc[4]  += a * w1.x; acc[5]  += a * w1.y; acc[6]  += a * w1.z; acc[7]  += a * w1.w;
            acc[8]  += a * w2.x; acc[9]  += a * w2.y; acc[10] += a * w2.z; acc[11] += a * w2.w;
        }
        __syncthreads();
    }

    int rg = prow * 32 + row;
    float mean = g_mean[rg], stdv = g_std[rg];
    float w = rev_w[c], rb = rev_b[c];
    float scale = stdv / w;
    #pragma unroll
    for (int j = 0; j < 12; j++) {
        int o = cg * 12 + j;
        float y = acc[j] + bh[kc * O_ + o];
        out[((size_t)row * O_ + o) * C_ + c] = (y - rb) * scale + mean;
    }
}

// ------------------------- launch ----------------------------------
extern "C" void kernel_launch(void* const* d_in, const int* in_sizes, int n_in,
                              void* d_out, int out_size) {
    const float* x     = (const float*)d_in[0];
    const float* rev_w = (const float*)d_in[1];
    const float* rev_b = (const float*)d_in[2];
    const float* W1    = (const float*)d_in[3];
    const float* b1    = (const float*)d_in[4];
    const float* W2    = (const float*)d_in[5];
    const float* b2    = (const float*)d_in[6];
    const float* Wh    = (const float*)d_in[7];
    const float* bh    = (const float*)d_in[8];
    const int*   assign = (const int*)d_in[9];
    float* out = (float*)d_out;

    cudaFuncSetAttribute(ffn_mma<true>,  cudaFuncAttributeMaxDynamicSharedMemorySize, FFN_SMEM);
    cudaFuncSetAttribute(ffn_mma<false>, cudaFuncAttributeMaxDynamicSharedMemorySize, FFN_SMEM);

    prep_kernel<<<1, 256>>>(assign);
    convW1_kernel<<<dim3(DFF_ / 32, KPAD / 32, KC_ * NL_), dim3(32, 8)>>>(W1);
    convW2_kernel<<<dim3(DFF_ / 32, KPAD / 32, KC_ * NL_), dim3(32, 8)>>>(W2);
    revin_kernel<<<MTOT, 128>>>(x, rev_w, rev_b);
    for (int l = 0; l < NL_; l++) {
        ffn_mma<true ><<<dim3(DFF_ / 128, MGRP), 128, FFN_SMEM>>>(b1, l);   // 8 x 134
        ffn_mma<false><<<dim3(3,          MGRP), 128, FFN_SMEM>>>(b2, l);   // 3 x 134 (N=112 tiles)
    }
    head_kernel<<<PROWS, 256>>>(Wh, bh, rev_w, rev_b, out);
}